// round 1
// baseline (speedup 1.0000x reference)
#include <cuda_runtime.h>
#include <math.h>

// Problem dims (fixed)
#define B_   64
#define S_   512
#define D_   256
#define ROWS (B_ * S_)          // 32768
#define WSZ  (D_ * D_)          // 65536 per-layer weight size

// ---------------------------------------------------------------------------
// Scratch (device globals; no allocation allowed)
// ---------------------------------------------------------------------------
__device__ float g_H[ROWS * D_];
__device__ float g_Q[ROWS * D_];
__device__ float g_K[ROWS * D_];
__device__ float g_V[ROWS * D_];
__device__ float g_O[ROWS * D_];
__device__ float g_T[ROWS * D_];
__device__ float g_C[ROWS * D_];
__device__ float g_F[ROWS * D_];
__device__ float g_E[(long)B_ * S_ * S_];   // 64 MB attention scores

// ---------------------------------------------------------------------------
// LayerNorm: one warp per row (D=256 -> 8 floats/lane via 2x float4)
// out = (res ? res : 0) + LN(in) * g + b
// ---------------------------------------------------------------------------
__global__ void ln_k(const float* __restrict__ in, const float* __restrict__ res,
                     const float* __restrict__ g, const float* __restrict__ b,
                     float* __restrict__ out, int rows)
{
    int warp = (blockIdx.x * blockDim.x + threadIdx.x) >> 5;
    int lane = threadIdx.x & 31;
    if (warp >= rows) return;

    const float4* x4 = (const float4*)(in + (long)warp * D_);
    float4 v0 = x4[lane];
    float4 v1 = x4[lane + 32];

    float s = v0.x + v0.y + v0.z + v0.w + v1.x + v1.y + v1.z + v1.w;
    #pragma unroll
    for (int o = 16; o; o >>= 1) s += __shfl_xor_sync(0xffffffffu, s, o);
    float mean = s * (1.0f / 256.0f);

    float d0x = v0.x - mean, d0y = v0.y - mean, d0z = v0.z - mean, d0w = v0.w - mean;
    float d1x = v1.x - mean, d1y = v1.y - mean, d1z = v1.z - mean, d1w = v1.w - mean;
    float q = d0x*d0x + d0y*d0y + d0z*d0z + d0w*d0w
            + d1x*d1x + d1y*d1y + d1z*d1z + d1w*d1w;
    #pragma unroll
    for (int o = 16; o; o >>= 1) q += __shfl_xor_sync(0xffffffffu, q, o);
    float inv = rsqrtf(q * (1.0f / 256.0f) + 1e-5f);

    const float4* g4 = (const float4*)g;
    const float4* b4 = (const float4*)b;
    float4 gv0 = g4[lane], gv1 = g4[lane + 32];
    float4 bv0 = b4[lane], bv1 = b4[lane + 32];

    float4 o0, o1;
    o0.x = d0x * inv * gv0.x + bv0.x;  o0.y = d0y * inv * gv0.y + bv0.y;
    o0.z = d0z * inv * gv0.z + bv0.z;  o0.w = d0w * inv * gv0.w + bv0.w;
    o1.x = d1x * inv * gv1.x + bv1.x;  o1.y = d1y * inv * gv1.y + bv1.y;
    o1.z = d1z * inv * gv1.z + bv1.z;  o1.w = d1w * inv * gv1.w + bv1.w;

    if (res) {
        const float4* r4 = (const float4*)(res + (long)warp * D_);
        float4 r0 = r4[lane], r1 = r4[lane + 32];
        o0.x += r0.x; o0.y += r0.y; o0.z += r0.z; o0.w += r0.w;
        o1.x += r1.x; o1.y += r1.y; o1.z += r1.z; o1.w += r1.w;
    }

    float4* out4 = (float4*)(out + (long)warp * D_);
    out4[lane]      = o0;
    out4[lane + 32] = o1;
}

// ---------------------------------------------------------------------------
// Softmax over rows of length 512: one warp per row (16 floats/lane)
// ---------------------------------------------------------------------------
__global__ void softmax_k(float* __restrict__ E, int rows)
{
    int warp = (blockIdx.x * blockDim.x + threadIdx.x) >> 5;
    int lane = threadIdx.x & 31;
    if (warp >= rows) return;

    float4* p = (float4*)(E + (long)warp * 512);
    float4 v[4];
    #pragma unroll
    for (int i = 0; i < 4; i++) v[i] = p[lane + 32 * i];

    float mx = -3.402823466e38f;
    #pragma unroll
    for (int i = 0; i < 4; i++) {
        mx = fmaxf(mx, fmaxf(fmaxf(v[i].x, v[i].y), fmaxf(v[i].z, v[i].w)));
    }
    #pragma unroll
    for (int o = 16; o; o >>= 1) mx = fmaxf(mx, __shfl_xor_sync(0xffffffffu, mx, o));

    float sum = 0.0f;
    #pragma unroll
    for (int i = 0; i < 4; i++) {
        v[i].x = expf(v[i].x - mx); v[i].y = expf(v[i].y - mx);
        v[i].z = expf(v[i].z - mx); v[i].w = expf(v[i].w - mx);
        sum += v[i].x + v[i].y + v[i].z + v[i].w;
    }
    #pragma unroll
    for (int o = 16; o; o >>= 1) sum += __shfl_xor_sync(0xffffffffu, sum, o);
    float r = 1.0f / sum;

    #pragma unroll
    for (int i = 0; i < 4; i++) {
        v[i].x *= r; v[i].y *= r; v[i].z *= r; v[i].w *= r;
        p[lane + 32 * i] = v[i];
    }
}

// ---------------------------------------------------------------------------
// SGEMM 128x128x8, 256 threads, 8x8 microtile, float4 loads.
// All dims assumed multiples of 128 (M,N) and 8 (K) -- true for this problem.
// EPI: 0 none | 1 +bias | 2 gelu(.+bias) | 3 res + (.+bias) | 4 attention score
// TB : B is [N,K] row-major (use for Q @ K^T)
// ---------------------------------------------------------------------------
template<int EPI, bool TB>
__global__ void __launch_bounds__(256, 2)
gemm_k(const float* __restrict__ A, const float* __restrict__ Bm,
       const float* __restrict__ bias, const float* __restrict__ res,
       float* __restrict__ C, int M, int N, int K,
       long sA, long sB, long sC,
       const int* __restrict__ mask, const float* __restrict__ btab)
{
    const int tid = threadIdx.x;
    const int bz  = blockIdx.z;
    A  += (long)bz * sA;
    Bm += (long)bz * sB;
    C  += (long)bz * sC;

    __shared__ float As[8][128];
    __shared__ float Bs[8][128];

    const int bm = blockIdx.y * 128;
    const int bn = blockIdx.x * 128;

    const int lr = tid >> 1;            // 0..127
    const int lc = (tid & 1) << 2;      // 0 or 4
    const int br = tid >> 5;            // 0..7
    const int bc = (tid & 31) << 2;     // 0..124

    const int tx = (tid & 15) << 3;     // col base 0..120
    const int ty = (tid >> 4) << 3;     // row base 0..120

    float acc[8][8];
    #pragma unroll
    for (int i = 0; i < 8; i++)
        #pragma unroll
        for (int j = 0; j < 8; j++) acc[i][j] = 0.0f;

    const float* Aptr = A + (long)(bm + lr) * K + lc;
    const float* Bptr = TB ? (Bm + (long)(bn + lr) * K + lc)
                           : (Bm + (long)br * N + bn + bc);

    for (int k0 = 0; k0 < K; k0 += 8) {
        float4 av = *(const float4*)(Aptr + k0);
        As[lc + 0][lr] = av.x; As[lc + 1][lr] = av.y;
        As[lc + 2][lr] = av.z; As[lc + 3][lr] = av.w;
        if (TB) {
            float4 bv = *(const float4*)(Bptr + k0);
            Bs[lc + 0][lr] = bv.x; Bs[lc + 1][lr] = bv.y;
            Bs[lc + 2][lr] = bv.z; Bs[lc + 3][lr] = bv.w;
        } else {
            float4 bv = *(const float4*)(Bptr + (long)k0 * N);
            *(float4*)&Bs[br][bc] = bv;
        }
        __syncthreads();

        #pragma unroll
        for (int kk = 0; kk < 8; kk++) {
            float ra[8], rb[8];
            #pragma unroll
            for (int i = 0; i < 8; i++) ra[i] = As[kk][ty + i];
            #pragma unroll
            for (int j = 0; j < 8; j++) rb[j] = Bs[kk][tx + j];
            #pragma unroll
            for (int i = 0; i < 8; i++)
                #pragma unroll
                for (int j = 0; j < 8; j++)
                    acc[i][j] = fmaf(ra[i], rb[j], acc[i][j]);
        }
        __syncthreads();
    }

    #pragma unroll
    for (int i = 0; i < 8; i++) {
        const int m = bm + ty + i;
        #pragma unroll
        for (int j = 0; j < 8; j++) {
            const int n = bn + tx + j;
            float v = acc[i][j];
            if (EPI == 1 || EPI == 2 || EPI == 3) v += bias[n];
            if (EPI == 2) v = 0.5f * v * (1.0f + erff(v * 0.70710678118654752f));
            if (EPI == 3) v += res[(long)m * N + n];
            if (EPI == 4) {
                // relative position bias: rel = k - q; bucket = rel<0 ? 511-rel : rel
                int rel = n - m;
                int bucket = (rel < 0) ? (511 - rel) : rel;
                v = v * 0.0625f + btab[bucket];              // 1/sqrt(256)
                if (mask[bz * S_ + n] == 0) v = -3.402823466e38f;
            }
            C[(long)m * N + n] = v;
        }
    }
}

// ---------------------------------------------------------------------------
// Launcher
// ---------------------------------------------------------------------------
extern "C" void kernel_launch(void* const* d_in, const int* in_sizes, int n_in,
                              void* d_out, int out_size)
{
    const float* x    = (const float*)d_in[0];
    const int*   mask = (const int*)  d_in[1];
    const float* btab = (const float*)d_in[2];
    const float* ln_g = (const float*)d_in[3];
    const float* ln_b = (const float*)d_in[4];
    const float* wq   = (const float*)d_in[5];
    const float* bq   = (const float*)d_in[6];
    const float* wk   = (const float*)d_in[7];
    const float* bk   = (const float*)d_in[8];
    const float* wv   = (const float*)d_in[9];
    const float* bv   = (const float*)d_in[10];
    const float* wo   = (const float*)d_in[11];
    const float* bo   = (const float*)d_in[12];
    const float* cmg  = (const float*)d_in[13];
    const float* cmb  = (const float*)d_in[14];
    const float* w1   = (const float*)d_in[15];
    const float* b1   = (const float*)d_in[16];
    const float* w2   = (const float*)d_in[17];
    const float* b2   = (const float*)d_in[18];
    float* xo = (float*)d_out;

    float *H, *Q, *Kb, *V, *O, *T, *Cb, *F, *E;
    cudaGetSymbolAddress((void**)&H,  g_H);
    cudaGetSymbolAddress((void**)&Q,  g_Q);
    cudaGetSymbolAddress((void**)&Kb, g_K);
    cudaGetSymbolAddress((void**)&V,  g_V);
    cudaGetSymbolAddress((void**)&O,  g_O);
    cudaGetSymbolAddress((void**)&T,  g_T);
    cudaGetSymbolAddress((void**)&Cb, g_C);
    cudaGetSymbolAddress((void**)&F,  g_F);
    cudaGetSymbolAddress((void**)&E,  g_E);

    const dim3 blk(256);
    const dim3 gProj(D_ / 128, ROWS / 128, 1);   // (2, 256)
    const dim3 gScore(S_ / 128, S_ / 128, B_);   // (4, 4, 64)
    const dim3 gAV(D_ / 128, S_ / 128, B_);      // (2, 4, 64)
    const int  rowBlocks = ROWS / 8;             // 4096 (8 warps/block)
    const long sQKV = (long)S_ * D_;             // 131072
    const long sE   = (long)S_ * S_;             // 262144

    for (int j = 0; j < 3; j++) {
        const float* xin = (j == 0) ? x : xo;
        const float* gj = ln_g + j * D_;
        const float* bj = ln_b + j * D_;

        // h = LN(x)
        ln_k<<<rowBlocks, 256>>>(xin, nullptr, gj, bj, H, ROWS);

        // q, k, v projections
        gemm_k<1, false><<<gProj, blk>>>(H, wq + j * WSZ, bq + j * D_, nullptr, Q,
                                         ROWS, D_, D_, 0, 0, 0, nullptr, nullptr);
        gemm_k<1, false><<<gProj, blk>>>(H, wk + j * WSZ, bk + j * D_, nullptr, Kb,
                                         ROWS, D_, D_, 0, 0, 0, nullptr, nullptr);
        gemm_k<1, false><<<gProj, blk>>>(H, wv + j * WSZ, bv + j * D_, nullptr, V,
                                         ROWS, D_, D_, 0, 0, 0, nullptr, nullptr);

        // e = q k^T / 16 + relpos_bias, masked
        gemm_k<4, true><<<gScore, blk>>>(Q, Kb, nullptr, nullptr, E,
                                         S_, S_, D_, sQKV, sQKV, sE, mask, btab);

        // a = softmax(e)
        softmax_k<<<rowBlocks, 256>>>(E, ROWS);

        // o = a @ v
        gemm_k<0, false><<<gAV, blk>>>(E, V, nullptr, nullptr, O,
                                       S_, D_, S_, sE, sQKV, sQKV, nullptr, nullptr);

        // t = o @ wo + bo
        gemm_k<1, false><<<gProj, blk>>>(O, wo + j * WSZ, bo + j * D_, nullptr, T,
                                         ROWS, D_, D_, 0, 0, 0, nullptr, nullptr);

        // x = h + LN(t)   (same gamma/beta as the first LN, per source)
        ln_k<<<rowBlocks, 256>>>(T, H, gj, bj, xo, ROWS);

        // c = LN_cm(x)
        ln_k<<<rowBlocks, 256>>>(xo, nullptr, cmg + j * D_, cmb + j * D_, Cb, ROWS);

        // f = gelu(c @ w1 + b1)   (exact gelu)
        gemm_k<2, false><<<gProj, blk>>>(Cb, w1 + j * WSZ, b1 + j * D_, nullptr, F,
                                         ROWS, D_, D_, 0, 0, 0, nullptr, nullptr);

        // x = x + f @ w2 + b2   (in-place residual: each element read once by writer)
        gemm_k<3, false><<<gProj, blk>>>(F, w2 + j * WSZ, b2 + j * D_, xo, xo,
                                         ROWS, D_, D_, 0, 0, 0, nullptr, nullptr);
    }
}

// round 2
// speedup vs baseline: 1.2115x; 1.2115x over previous
#include <cuda_runtime.h>
#include <math.h>

// Problem dims (fixed)
#define B_   64
#define S_   512
#define D_   256
#define ROWS (B_ * S_)          // 32768
#define WSZ  (D_ * D_)          // 65536 per-layer weight size

// ---------------------------------------------------------------------------
// Scratch (device globals; no allocation allowed)
// ---------------------------------------------------------------------------
__device__ float g_H[ROWS * D_];
__device__ float g_Q[ROWS * D_];
__device__ float g_K[ROWS * D_];
__device__ float g_V[ROWS * D_];
__device__ float g_O[ROWS * D_];
__device__ float g_T[ROWS * D_];
__device__ float g_C[ROWS * D_];
__device__ float g_F[ROWS * D_];
__device__ float g_E[(long)B_ * S_ * S_];   // 64 MB attention scores

// ---------------------------------------------------------------------------
// LayerNorm: one warp per row (D=256 -> 8 floats/lane via 2x float4)
// out = (res ? res : 0) + LN(in) * g + b
// ---------------------------------------------------------------------------
__global__ void ln_k(const float* __restrict__ in, const float* __restrict__ res,
                     const float* __restrict__ g, const float* __restrict__ b,
                     float* __restrict__ out, int rows)
{
    int warp = (blockIdx.x * blockDim.x + threadIdx.x) >> 5;
    int lane = threadIdx.x & 31;
    if (warp >= rows) return;

    const float4* x4 = (const float4*)(in + (long)warp * D_);
    float4 v0 = x4[lane];
    float4 v1 = x4[lane + 32];

    float s = v0.x + v0.y + v0.z + v0.w + v1.x + v1.y + v1.z + v1.w;
    #pragma unroll
    for (int o = 16; o; o >>= 1) s += __shfl_xor_sync(0xffffffffu, s, o);
    float mean = s * (1.0f / 256.0f);

    float d0x = v0.x - mean, d0y = v0.y - mean, d0z = v0.z - mean, d0w = v0.w - mean;
    float d1x = v1.x - mean, d1y = v1.y - mean, d1z = v1.z - mean, d1w = v1.w - mean;
    float q = d0x*d0x + d0y*d0y + d0z*d0z + d0w*d0w
            + d1x*d1x + d1y*d1y + d1z*d1z + d1w*d1w;
    #pragma unroll
    for (int o = 16; o; o >>= 1) q += __shfl_xor_sync(0xffffffffu, q, o);
    float inv = rsqrtf(q * (1.0f / 256.0f) + 1e-5f);

    const float4* g4 = (const float4*)g;
    const float4* b4 = (const float4*)b;
    float4 gv0 = g4[lane], gv1 = g4[lane + 32];
    float4 bv0 = b4[lane], bv1 = b4[lane + 32];

    float4 o0, o1;
    o0.x = d0x * inv * gv0.x + bv0.x;  o0.y = d0y * inv * gv0.y + bv0.y;
    o0.z = d0z * inv * gv0.z + bv0.z;  o0.w = d0w * inv * gv0.w + bv0.w;
    o1.x = d1x * inv * gv1.x + bv1.x;  o1.y = d1y * inv * gv1.y + bv1.y;
    o1.z = d1z * inv * gv1.z + bv1.z;  o1.w = d1w * inv * gv1.w + bv1.w;

    if (res) {
        const float4* r4 = (const float4*)(res + (long)warp * D_);
        float4 r0 = r4[lane], r1 = r4[lane + 32];
        o0.x += r0.x; o0.y += r0.y; o0.z += r0.z; o0.w += r0.w;
        o1.x += r1.x; o1.y += r1.y; o1.z += r1.z; o1.w += r1.w;
    }

    float4* out4 = (float4*)(out + (long)warp * D_);
    out4[lane]      = o0;
    out4[lane + 32] = o1;
}

// ---------------------------------------------------------------------------
// Softmax over rows of length 512: one warp per row (16 floats/lane)
// ---------------------------------------------------------------------------
__global__ void softmax_k(float* __restrict__ E, int rows)
{
    int warp = (blockIdx.x * blockDim.x + threadIdx.x) >> 5;
    int lane = threadIdx.x & 31;
    if (warp >= rows) return;

    float4* p = (float4*)(E + (long)warp * 512);
    float4 v[4];
    #pragma unroll
    for (int i = 0; i < 4; i++) v[i] = p[lane + 32 * i];

    float mx = -3.402823466e38f;
    #pragma unroll
    for (int i = 0; i < 4; i++) {
        mx = fmaxf(mx, fmaxf(fmaxf(v[i].x, v[i].y), fmaxf(v[i].z, v[i].w)));
    }
    #pragma unroll
    for (int o = 16; o; o >>= 1) mx = fmaxf(mx, __shfl_xor_sync(0xffffffffu, mx, o));

    float sum = 0.0f;
    #pragma unroll
    for (int i = 0; i < 4; i++) {
        v[i].x = expf(v[i].x - mx); v[i].y = expf(v[i].y - mx);
        v[i].z = expf(v[i].z - mx); v[i].w = expf(v[i].w - mx);
        sum += v[i].x + v[i].y + v[i].z + v[i].w;
    }
    #pragma unroll
    for (int o = 16; o; o >>= 1) sum += __shfl_xor_sync(0xffffffffu, sum, o);
    float r = 1.0f / sum;

    #pragma unroll
    for (int i = 0; i < 4; i++) {
        v[i].x *= r; v[i].y *= r; v[i].z *= r; v[i].w *= r;
        p[lane + 32 * i] = v[i];
    }
}

// ---------------------------------------------------------------------------
// SGEMM 128x128x16, 256 threads, 8x8 microtile, double-buffered smem,
// float4 smem fragment loads, float4 epilogue stores.
// All dims multiples of 128 (M,N) and 16 (K) -- true for this problem.
// EPI: 0 none | 1 +bias | 2 gelu(.+bias) | 3 res + (.+bias) | 4 attention score
// TB : B is [N,K] row-major (use for Q @ K^T)
// ---------------------------------------------------------------------------
template<int EPI, bool TB>
__global__ void __launch_bounds__(256, 2)
gemm_k(const float* __restrict__ A, const float* __restrict__ Bm,
       const float* __restrict__ bias, const float* __restrict__ res,
       float* __restrict__ C, int M, int N, int K,
       long sA, long sB, long sC,
       const int* __restrict__ mask, const float* __restrict__ btab)
{
    const int tid = threadIdx.x;
    const int bz  = blockIdx.z;
    A  += (long)bz * sA;
    Bm += (long)bz * sB;
    C  += (long)bz * sC;

    __shared__ float As[2][16][128];
    __shared__ float Bs[2][16][128];

    const int bm = blockIdx.y * 128;
    const int bn = blockIdx.x * 128;

    // ---- global load indices ----
    // A tile (128 rows x 16 cols): ar in [0,64)+{0,64}, ac in {0,4,8,12}
    const int ar = tid >> 2;
    const int ac = (tid & 3) << 2;
    // B tile (!TB): (16 rows x 128 cols): br in [0,8)+{0,8}, bc 4-wide
    const int br = tid >> 5;
    const int bc = (tid & 31) << 2;

    // ---- compute mapping ----
    const int tx = (tid & 15) << 3;     // col base 0..120
    const int ty = (tid >> 4) << 3;     // row base 0..120

    float acc[8][8];
    #pragma unroll
    for (int i = 0; i < 8; i++)
        #pragma unroll
        for (int j = 0; j < 8; j++) acc[i][j] = 0.0f;

    const float* Ap0 = A + (long)(bm + ar) * K + ac;
    const float* Ap1 = A + (long)(bm + ar + 64) * K + ac;
    const float* Bp0;
    const float* Bp1;
    if (TB) {
        Bp0 = Bm + (long)(bn + ar) * K + ac;
        Bp1 = Bm + (long)(bn + ar + 64) * K + ac;
    } else {
        Bp0 = Bm + (long)br * N + bn + bc;
        Bp1 = Bm + (long)(br + 8) * N + bn + bc;
    }

    // ---- prologue: load tile 0 into buffer 0 ----
    {
        float4 a0 = *(const float4*)Ap0;
        float4 a1 = *(const float4*)Ap1;
        As[0][ac + 0][ar] = a0.x; As[0][ac + 1][ar] = a0.y;
        As[0][ac + 2][ar] = a0.z; As[0][ac + 3][ar] = a0.w;
        As[0][ac + 0][ar + 64] = a1.x; As[0][ac + 1][ar + 64] = a1.y;
        As[0][ac + 2][ar + 64] = a1.z; As[0][ac + 3][ar + 64] = a1.w;
        if (TB) {
            float4 b0 = *(const float4*)Bp0;
            float4 b1 = *(const float4*)Bp1;
            Bs[0][ac + 0][ar] = b0.x; Bs[0][ac + 1][ar] = b0.y;
            Bs[0][ac + 2][ar] = b0.z; Bs[0][ac + 3][ar] = b0.w;
            Bs[0][ac + 0][ar + 64] = b1.x; Bs[0][ac + 1][ar + 64] = b1.y;
            Bs[0][ac + 2][ar + 64] = b1.z; Bs[0][ac + 3][ar + 64] = b1.w;
        } else {
            *(float4*)&Bs[0][br][bc]     = *(const float4*)Bp0;
            *(float4*)&Bs[0][br + 8][bc] = *(const float4*)Bp1;
        }
    }
    __syncthreads();

    int buf = 0;
    for (int k0 = 0; k0 < K; k0 += 16) {
        const int knext = k0 + 16;
        float4 a0, a1, b0, b1;
        const bool more = (knext < K);
        if (more) {
            if (TB) {
                a0 = *(const float4*)(Ap0 + knext);
                a1 = *(const float4*)(Ap1 + knext);
                b0 = *(const float4*)(Bp0 + knext);
                b1 = *(const float4*)(Bp1 + knext);
            } else {
                a0 = *(const float4*)(Ap0 + knext);
                a1 = *(const float4*)(Ap1 + knext);
                b0 = *(const float4*)(Bp0 + (long)knext * N);
                b1 = *(const float4*)(Bp1 + (long)knext * N);
            }
        }

        #pragma unroll
        for (int kk = 0; kk < 16; kk++) {
            float4 af0 = *(const float4*)&As[buf][kk][ty];
            float4 af1 = *(const float4*)&As[buf][kk][ty + 4];
            float4 bf0 = *(const float4*)&Bs[buf][kk][tx];
            float4 bf1 = *(const float4*)&Bs[buf][kk][tx + 4];
            float ra[8] = {af0.x, af0.y, af0.z, af0.w, af1.x, af1.y, af1.z, af1.w};
            float rb[8] = {bf0.x, bf0.y, bf0.z, bf0.w, bf1.x, bf1.y, bf1.z, bf1.w};
            #pragma unroll
            for (int i = 0; i < 8; i++)
                #pragma unroll
                for (int j = 0; j < 8; j++)
                    acc[i][j] = fmaf(ra[i], rb[j], acc[i][j]);
        }

        if (!more) break;
        const int nb = buf ^ 1;
        As[nb][ac + 0][ar] = a0.x; As[nb][ac + 1][ar] = a0.y;
        As[nb][ac + 2][ar] = a0.z; As[nb][ac + 3][ar] = a0.w;
        As[nb][ac + 0][ar + 64] = a1.x; As[nb][ac + 1][ar + 64] = a1.y;
        As[nb][ac + 2][ar + 64] = a1.z; As[nb][ac + 3][ar + 64] = a1.w;
        if (TB) {
            Bs[nb][ac + 0][ar] = b0.x; Bs[nb][ac + 1][ar] = b0.y;
            Bs[nb][ac + 2][ar] = b0.z; Bs[nb][ac + 3][ar] = b0.w;
            Bs[nb][ac + 0][ar + 64] = b1.x; Bs[nb][ac + 1][ar + 64] = b1.y;
            Bs[nb][ac + 2][ar + 64] = b1.z; Bs[nb][ac + 3][ar + 64] = b1.w;
        } else {
            *(float4*)&Bs[nb][br][bc]     = b0;
            *(float4*)&Bs[nb][br + 8][bc] = b1;
        }
        __syncthreads();
        buf = nb;
    }

    // ---- epilogue (vectorized) ----
    float4 bias0, bias1;
    if (EPI == 1 || EPI == 2 || EPI == 3) {
        bias0 = *(const float4*)(bias + bn + tx);
        bias1 = *(const float4*)(bias + bn + tx + 4);
    }
    int mk0 = 0, mk1 = 0;
    if (EPI == 4) {
        // key-side mask per column (same for all rows of this block)
        mk0 = mask[bz * S_ + bn + tx];     // will re-read per column below
    }
    (void)mk0; (void)mk1;

    #pragma unroll
    for (int i = 0; i < 8; i++) {
        const int m = bm + ty + i;
        float v[8];
        #pragma unroll
        for (int j = 0; j < 8; j++) v[j] = acc[i][j];

        if (EPI == 1 || EPI == 2 || EPI == 3) {
            v[0] += bias0.x; v[1] += bias0.y; v[2] += bias0.z; v[3] += bias0.w;
            v[4] += bias1.x; v[5] += bias1.y; v[6] += bias1.z; v[7] += bias1.w;
        }
        if (EPI == 2) {
            #pragma unroll
            for (int j = 0; j < 8; j++)
                v[j] = 0.5f * v[j] * (1.0f + erff(v[j] * 0.70710678118654752f));
        }
        if (EPI == 3) {
            float4 r0 = *(const float4*)(res + (long)m * N + bn + tx);
            float4 r1 = *(const float4*)(res + (long)m * N + bn + tx + 4);
            v[0] += r0.x; v[1] += r0.y; v[2] += r0.z; v[3] += r0.w;
            v[4] += r1.x; v[5] += r1.y; v[6] += r1.z; v[7] += r1.w;
        }
        if (EPI == 4) {
            #pragma unroll
            for (int j = 0; j < 8; j++) {
                const int n = bn + tx + j;
                int rel = n - m;
                int bucket = (rel < 0) ? (511 - rel) : rel;
                v[j] = v[j] * 0.0625f + btab[bucket];          // 1/sqrt(256)
                if (mask[bz * S_ + n] == 0) v[j] = -3.402823466e38f;
            }
        }
        float4 o0 = {v[0], v[1], v[2], v[3]};
        float4 o1 = {v[4], v[5], v[6], v[7]};
        *(float4*)(C + (long)m * N + bn + tx)     = o0;
        *(float4*)(C + (long)m * N + bn + tx + 4) = o1;
    }
}

// ---------------------------------------------------------------------------
// Launcher
// ---------------------------------------------------------------------------
extern "C" void kernel_launch(void* const* d_in, const int* in_sizes, int n_in,
                              void* d_out, int out_size)
{
    const float* x    = (const float*)d_in[0];
    const int*   mask = (const int*)  d_in[1];
    const float* btab = (const float*)d_in[2];
    const float* ln_g = (const float*)d_in[3];
    const float* ln_b = (const float*)d_in[4];
    const float* wq   = (const float*)d_in[5];
    const float* bq   = (const float*)d_in[6];
    const float* wk   = (const float*)d_in[7];
    const float* bk   = (const float*)d_in[8];
    const float* wv   = (const float*)d_in[9];
    const float* bv   = (const float*)d_in[10];
    const float* wo   = (const float*)d_in[11];
    const float* bo   = (const float*)d_in[12];
    const float* cmg  = (const float*)d_in[13];
    const float* cmb  = (const float*)d_in[14];
    const float* w1   = (const float*)d_in[15];
    const float* b1   = (const float*)d_in[16];
    const float* w2   = (const float*)d_in[17];
    const float* b2   = (const float*)d_in[18];
    float* xo = (float*)d_out;

    float *H, *Q, *Kb, *V, *O, *T, *Cb, *F, *E;
    cudaGetSymbolAddress((void**)&H,  g_H);
    cudaGetSymbolAddress((void**)&Q,  g_Q);
    cudaGetSymbolAddress((void**)&Kb, g_K);
    cudaGetSymbolAddress((void**)&V,  g_V);
    cudaGetSymbolAddress((void**)&O,  g_O);
    cudaGetSymbolAddress((void**)&T,  g_T);
    cudaGetSymbolAddress((void**)&Cb, g_C);
    cudaGetSymbolAddress((void**)&F,  g_F);
    cudaGetSymbolAddress((void**)&E,  g_E);

    const dim3 blk(256);
    const dim3 gProj(D_ / 128, ROWS / 128, 1);   // (2, 256)
    const dim3 gScore(S_ / 128, S_ / 128, B_);   // (4, 4, 64)
    const dim3 gAV(D_ / 128, S_ / 128, B_);      // (2, 4, 64)
    const int  rowBlocks = ROWS / 8;             // 4096 (8 warps/block)
    const long sQKV = (long)S_ * D_;             // 131072
    const long sE   = (long)S_ * S_;             // 262144

    for (int j = 0; j < 3; j++) {
        const float* xin = (j == 0) ? x : xo;
        const float* gj = ln_g + j * D_;
        const float* bj = ln_b + j * D_;

        // h = LN(x)
        ln_k<<<rowBlocks, 256>>>(xin, nullptr, gj, bj, H, ROWS);

        // q, k, v projections
        gemm_k<1, false><<<gProj, blk>>>(H, wq + j * WSZ, bq + j * D_, nullptr, Q,
                                         ROWS, D_, D_, 0, 0, 0, nullptr, nullptr);
        gemm_k<1, false><<<gProj, blk>>>(H, wk + j * WSZ, bk + j * D_, nullptr, Kb,
                                         ROWS, D_, D_, 0, 0, 0, nullptr, nullptr);
        gemm_k<1, false><<<gProj, blk>>>(H, wv + j * WSZ, bv + j * D_, nullptr, V,
                                         ROWS, D_, D_, 0, 0, 0, nullptr, nullptr);

        // e = q k^T / 16 + relpos_bias, masked
        gemm_k<4, true><<<gScore, blk>>>(Q, Kb, nullptr, nullptr, E,
                                         S_, S_, D_, sQKV, sQKV, sE, mask, btab);

        // a = softmax(e)
        softmax_k<<<rowBlocks, 256>>>(E, ROWS);

        // o = a @ v
        gemm_k<0, false><<<gAV, blk>>>(E, V, nullptr, nullptr, O,
                                       S_, D_, S_, sE, sQKV, sQKV, nullptr, nullptr);

        // t = o @ wo + bo
        gemm_k<1, false><<<gProj, blk>>>(O, wo + j * WSZ, bo + j * D_, nullptr, T,
                                         ROWS, D_, D_, 0, 0, 0, nullptr, nullptr);

        // x = h + LN(t)   (same gamma/beta as the first LN, per source)
        ln_k<<<rowBlocks, 256>>>(T, H, gj, bj, xo, ROWS);

        // c = LN_cm(x)
        ln_k<<<rowBlocks, 256>>>(xo, nullptr, cmg + j * D_, cmb + j * D_, Cb, ROWS);

        // f = gelu(c @ w1 + b1)   (exact gelu)
        gemm_k<2, false><<<gProj, blk>>>(Cb, w1 + j * WSZ, b1 + j * D_, nullptr, F,
                                         ROWS, D_, D_, 0, 0, 0, nullptr, nullptr);

        // x = x + f @ w2 + b2   (in-place residual: each element read once by writer)
        gemm_k<3, false><<<gProj, blk>>>(F, w2 + j * WSZ, b2 + j * D_, xo, xo,
                                         ROWS, D_, D_, 0, 0, 0, nullptr, nullptr);
    }
}

// round 3
// speedup vs baseline: 1.3857x; 1.1437x over previous
#include <cuda_runtime.h>
#include <math.h>
#include <stdint.h>

// Problem dims (fixed)
#define B_   64
#define S_   512
#define D_   256
#define ROWS (B_ * S_)          // 32768
#define WSZ  (D_ * D_)          // 65536 per-layer weight size

// ---------------------------------------------------------------------------
// Scratch (device globals; no allocation allowed)
// ---------------------------------------------------------------------------
__device__ float g_H[ROWS * D_];
__device__ float g_Q[ROWS * D_];
__device__ float g_K[ROWS * D_];
__device__ float g_V[ROWS * D_];
__device__ float g_O[ROWS * D_];
__device__ float g_T[ROWS * D_];
__device__ float g_C[ROWS * D_];
__device__ float g_F[ROWS * D_];
__device__ float g_E[(long)B_ * S_ * S_];   // 64 MB attention scores

// ---------------------------------------------------------------------------
// helpers
// ---------------------------------------------------------------------------
__device__ __forceinline__ uint32_t f2tf(float x) {
    uint32_t r;
    asm("cvt.rna.tf32.f32 %0, %1;" : "=r"(r) : "f"(x));
    return r;
}

__device__ __forceinline__ void mma_tf32(float* d, const uint32_t* a, const uint32_t* b) {
    asm volatile(
        "mma.sync.aligned.m16n8k8.row.col.f32.tf32.tf32.f32 "
        "{%0,%1,%2,%3}, {%4,%5,%6,%7}, {%8,%9}, {%0,%1,%2,%3};"
        : "+f"(d[0]), "+f"(d[1]), "+f"(d[2]), "+f"(d[3])
        : "r"(a[0]), "r"(a[1]), "r"(a[2]), "r"(a[3]), "r"(b[0]), "r"(b[1]));
}

// ---------------------------------------------------------------------------
// LayerNorm: one warp per row. out = (res ? res : 0) + LN(in) * g + b
// ---------------------------------------------------------------------------
__global__ void ln_k(const float* __restrict__ in, const float* __restrict__ res,
                     const float* __restrict__ g, const float* __restrict__ b,
                     float* __restrict__ out, int rows)
{
    int warp = (blockIdx.x * blockDim.x + threadIdx.x) >> 5;
    int lane = threadIdx.x & 31;
    if (warp >= rows) return;

    const float4* x4 = (const float4*)(in + (long)warp * D_);
    float4 v0 = x4[lane];
    float4 v1 = x4[lane + 32];

    float s = v0.x + v0.y + v0.z + v0.w + v1.x + v1.y + v1.z + v1.w;
    #pragma unroll
    for (int o = 16; o; o >>= 1) s += __shfl_xor_sync(0xffffffffu, s, o);
    float mean = s * (1.0f / 256.0f);

    float d0x = v0.x - mean, d0y = v0.y - mean, d0z = v0.z - mean, d0w = v0.w - mean;
    float d1x = v1.x - mean, d1y = v1.y - mean, d1z = v1.z - mean, d1w = v1.w - mean;
    float q = d0x*d0x + d0y*d0y + d0z*d0z + d0w*d0w
            + d1x*d1x + d1y*d1y + d1z*d1z + d1w*d1w;
    #pragma unroll
    for (int o = 16; o; o >>= 1) q += __shfl_xor_sync(0xffffffffu, q, o);
    float inv = rsqrtf(q * (1.0f / 256.0f) + 1e-5f);

    const float4* g4 = (const float4*)g;
    const float4* b4 = (const float4*)b;
    float4 gv0 = g4[lane], gv1 = g4[lane + 32];
    float4 bv0 = b4[lane], bv1 = b4[lane + 32];

    float4 o0, o1;
    o0.x = d0x * inv * gv0.x + bv0.x;  o0.y = d0y * inv * gv0.y + bv0.y;
    o0.z = d0z * inv * gv0.z + bv0.z;  o0.w = d0w * inv * gv0.w + bv0.w;
    o1.x = d1x * inv * gv1.x + bv1.x;  o1.y = d1y * inv * gv1.y + bv1.y;
    o1.z = d1z * inv * gv1.z + bv1.z;  o1.w = d1w * inv * gv1.w + bv1.w;

    if (res) {
        const float4* r4 = (const float4*)(res + (long)warp * D_);
        float4 r0 = r4[lane], r1 = r4[lane + 32];
        o0.x += r0.x; o0.y += r0.y; o0.z += r0.z; o0.w += r0.w;
        o1.x += r1.x; o1.y += r1.y; o1.z += r1.z; o1.w += r1.w;
    }

    float4* out4 = (float4*)(out + (long)warp * D_);
    out4[lane]      = o0;
    out4[lane + 32] = o1;
}

// ---------------------------------------------------------------------------
// Softmax over rows of length 512: one warp per row
// ---------------------------------------------------------------------------
__global__ void softmax_k(float* __restrict__ E, int rows)
{
    int warp = (blockIdx.x * blockDim.x + threadIdx.x) >> 5;
    int lane = threadIdx.x & 31;
    if (warp >= rows) return;

    float4* p = (float4*)(E + (long)warp * 512);
    float4 v[4];
    #pragma unroll
    for (int i = 0; i < 4; i++) v[i] = p[lane + 32 * i];

    float mx = -3.402823466e38f;
    #pragma unroll
    for (int i = 0; i < 4; i++)
        mx = fmaxf(mx, fmaxf(fmaxf(v[i].x, v[i].y), fmaxf(v[i].z, v[i].w)));
    #pragma unroll
    for (int o = 16; o; o >>= 1) mx = fmaxf(mx, __shfl_xor_sync(0xffffffffu, mx, o));

    float sum = 0.0f;
    #pragma unroll
    for (int i = 0; i < 4; i++) {
        v[i].x = expf(v[i].x - mx); v[i].y = expf(v[i].y - mx);
        v[i].z = expf(v[i].z - mx); v[i].w = expf(v[i].w - mx);
        sum += v[i].x + v[i].y + v[i].z + v[i].w;
    }
    #pragma unroll
    for (int o = 16; o; o >>= 1) sum += __shfl_xor_sync(0xffffffffu, sum, o);
    float r = 1.0f / sum;

    #pragma unroll
    for (int i = 0; i < 4; i++) {
        v[i].x *= r; v[i].y *= r; v[i].z *= r; v[i].w *= r;
        p[lane + 32 * i] = v[i];
    }
}

// ---------------------------------------------------------------------------
// TF32 tensor-core GEMM 128x128x16, 256 threads (8 warps, 2x4), warp 64x32,
// double-buffered, fragment-packed smem (conflict-free LDS.128/LDS.64).
// EPI: 0 none | 1 +bias | 2 gelu(.+bias) | 3 res + (.+bias) | 4 attention score
// TB : B is [N,K] row-major (Q @ K^T)
// A-frag smem layout: tile(kb,mb)=(kb*8+mb)*128, elem = t*4 + reg
// B-frag smem layout: tile(kb,nb)=(kb*16+nb)*64, elem = t*2 + reg
// ---------------------------------------------------------------------------
template<int EPI, bool TB>
__global__ void __launch_bounds__(256, 2)
gemm_k(const float* __restrict__ A, const float* __restrict__ Bm,
       const float* __restrict__ bias, const float* __restrict__ res,
       float* __restrict__ C, int M, int N, int K,
       long sA, long sB, long sC,
       const int* __restrict__ mask, const float* __restrict__ btab)
{
    const int tid  = threadIdx.x;
    const int lane = tid & 31;
    const int wm   = (tid >> 5) & 1;    // warp row (0..1) -> 64 rows
    const int wn   = tid >> 6;          // warp col (0..3) -> 32 cols
    const int bz   = blockIdx.z;
    A  += (long)bz * sA;
    Bm += (long)bz * sB;
    C  += (long)bz * sC;

    __shared__ uint32_t As[2][2048];
    __shared__ uint32_t Bs[2][2048];

    const int bm = blockIdx.y * 128;
    const int bn = blockIdx.x * 128;

    // ---- staging indices ----
    const int ar = tid >> 2;            // 0..63
    const int ac = (tid & 3) << 2;      // 0,4,8,12
    const int br = tid >> 5;            // 0..7
    const int bc = (tid & 31) << 2;     // 0..124

    // A staging smem bases (rows ar and ar+64, k-chunk ac)
    const int a_kb    = ac >> 3;
    const int a_creg2 = (ac & 4) >> 1;                   // 2*creg
    const int baseA0  = (a_kb * 8 + (ar >> 4)) * 128
                      + (ar & 7) * 16 + ((ar >> 3) & 1) + a_creg2;
    const int baseA1  = baseA0 + 4 * 128;                // mb += 4

    // B staging smem bases
    int baseB0, baseB1, bStride;                         // per-element stride
    if (TB) {   // rows n = ar, ar+64 ; cols ac..ac+3 (k)
        const int reg = (ac >> 2) & 1;
        baseB0 = (a_kb * 16 + (ar >> 3)) * 64 + (ar & 7) * 8 + reg;
        baseB1 = baseB0 + 8 * 64;                        // nb += 8
        bStride = 2;                                     // t += 1 per k... (kc3 = i)
    } else {    // rows k = br, br+8 ; cols bc..bc+3 (n)
        baseB0 = (0 * 16 + (bc >> 3)) * 64 + (bc & 7) * 8 + (br & 3) * 2 + (br >> 2);
        baseB1 = baseB0 + 16 * 64;                       // kb = 1
        bStride = 8;                                     // nn += 1 per n
    }

    // global pointers
    const float* Ap0 = A + (long)(bm + ar) * K + ac;
    const float* Ap1 = A + (long)(bm + ar + 64) * K + ac;
    const float* Bp0;
    const float* Bp1;
    if (TB) {
        Bp0 = Bm + (long)(bn + ar) * K + ac;
        Bp1 = Bm + (long)(bn + ar + 64) * K + ac;
    } else {
        Bp0 = Bm + (long)br * N + bn + bc;
        Bp1 = Bm + (long)(br + 8) * N + bn + bc;
    }

    float acc[4][4][4];
    #pragma unroll
    for (int i = 0; i < 4; i++)
        #pragma unroll
        for (int j = 0; j < 4; j++)
            #pragma unroll
            for (int r = 0; r < 4; r++) acc[i][j][r] = 0.0f;

    // ---- prologue: stage tile 0 ----
    {
        float4 a0 = *(const float4*)Ap0;
        float4 a1 = *(const float4*)Ap1;
        float4 b0, b1;
        if (TB) { b0 = *(const float4*)Bp0; b1 = *(const float4*)Bp1; }
        else    { b0 = *(const float4*)Bp0; b1 = *(const float4*)Bp1; }
        const float av0[4] = {a0.x, a0.y, a0.z, a0.w};
        const float av1[4] = {a1.x, a1.y, a1.z, a1.w};
        const float bv0[4] = {b0.x, b0.y, b0.z, b0.w};
        const float bv1[4] = {b1.x, b1.y, b1.z, b1.w};
        #pragma unroll
        for (int i = 0; i < 4; i++) {
            As[0][baseA0 + 4 * i] = f2tf(av0[i]);
            As[0][baseA1 + 4 * i] = f2tf(av1[i]);
            Bs[0][baseB0 + bStride * i] = f2tf(bv0[i]);
            Bs[0][baseB1 + bStride * i] = f2tf(bv1[i]);
        }
    }
    __syncthreads();

    int buf = 0;
    for (int k0 = 0; k0 < K; k0 += 16) {
        const int knext = k0 + 16;
        const bool more = (knext < K);
        float4 a0, a1, b0, b1;
        if (more) {
            a0 = *(const float4*)(Ap0 + knext);
            a1 = *(const float4*)(Ap1 + knext);
            if (TB) {
                b0 = *(const float4*)(Bp0 + knext);
                b1 = *(const float4*)(Bp1 + knext);
            } else {
                b0 = *(const float4*)(Bp0 + (long)knext * N);
                b1 = *(const float4*)(Bp1 + (long)knext * N);
            }
        }

        // ---- compute two k8 steps from this buffer ----
        #pragma unroll
        for (int kb = 0; kb < 2; kb++) {
            uint32_t af[4][4];
            uint32_t bf[4][2];
            #pragma unroll
            for (int ma = 0; ma < 4; ma++) {
                const uint32_t* p = &As[buf][(kb * 8 + wm * 4 + ma) * 128 + lane * 4];
                uint4 t = *(const uint4*)p;
                af[ma][0] = t.x; af[ma][1] = t.y; af[ma][2] = t.z; af[ma][3] = t.w;
            }
            #pragma unroll
            for (int nb = 0; nb < 4; nb++) {
                const uint32_t* p = &Bs[buf][(kb * 16 + wn * 4 + nb) * 64 + lane * 2];
                uint2 t = *(const uint2*)p;
                bf[nb][0] = t.x; bf[nb][1] = t.y;
            }
            #pragma unroll
            for (int ma = 0; ma < 4; ma++)
                #pragma unroll
                for (int nb = 0; nb < 4; nb++)
                    mma_tf32(acc[ma][nb], af[ma], bf[nb]);
        }

        if (!more) break;
        const int nb2 = buf ^ 1;
        const float av0[4] = {a0.x, a0.y, a0.z, a0.w};
        const float av1[4] = {a1.x, a1.y, a1.z, a1.w};
        const float bv0[4] = {b0.x, b0.y, b0.z, b0.w};
        const float bv1[4] = {b1.x, b1.y, b1.z, b1.w};
        #pragma unroll
        for (int i = 0; i < 4; i++) {
            As[nb2][baseA0 + 4 * i] = f2tf(av0[i]);
            As[nb2][baseA1 + 4 * i] = f2tf(av1[i]);
            Bs[nb2][baseB0 + bStride * i] = f2tf(bv0[i]);
            Bs[nb2][baseB1 + bStride * i] = f2tf(bv1[i]);
        }
        __syncthreads();
        buf = nb2;
    }

    // ---- epilogue ----
    #pragma unroll
    for (int nb = 0; nb < 4; nb++) {
        const int col = bn + wn * 32 + nb * 8 + (lane & 3) * 2;

        float2 bias2 = {0.0f, 0.0f};
        if (EPI == 1 || EPI == 2 || EPI == 3)
            bias2 = *(const float2*)(bias + col);
        int mk0 = 0, mk1 = 0;
        if (EPI == 4) {
            mk0 = mask[bz * S_ + col];
            mk1 = mask[bz * S_ + col + 1];
        }

        #pragma unroll
        for (int ma = 0; ma < 4; ma++) {
            const int r0 = bm + wm * 64 + ma * 16 + (lane >> 2);
            const int r1 = r0 + 8;
            float d0 = acc[ma][nb][0], d1 = acc[ma][nb][1];
            float d2 = acc[ma][nb][2], d3 = acc[ma][nb][3];

            if (EPI == 1 || EPI == 2 || EPI == 3) {
                d0 += bias2.x; d1 += bias2.y;
                d2 += bias2.x; d3 += bias2.y;
            }
            if (EPI == 2) {
                d0 = 0.5f * d0 * (1.0f + erff(d0 * 0.70710678118654752f));
                d1 = 0.5f * d1 * (1.0f + erff(d1 * 0.70710678118654752f));
                d2 = 0.5f * d2 * (1.0f + erff(d2 * 0.70710678118654752f));
                d3 = 0.5f * d3 * (1.0f + erff(d3 * 0.70710678118654752f));
            }
            if (EPI == 3) {
                float2 ra = *(const float2*)(res + (long)r0 * N + col);
                float2 rb = *(const float2*)(res + (long)r1 * N + col);
                d0 += ra.x; d1 += ra.y; d2 += rb.x; d3 += rb.y;
            }
            if (EPI == 4) {
                int rel0 = col - r0;
                int rel1 = col + 1 - r0;
                int rel2 = col - r1;
                int rel3 = col + 1 - r1;
                int bk0 = (rel0 < 0) ? (511 - rel0) : rel0;
                int bk1 = (rel1 < 0) ? (511 - rel1) : rel1;
                int bk2 = (rel2 < 0) ? (511 - rel2) : rel2;
                int bk3 = (rel3 < 0) ? (511 - rel3) : rel3;
                d0 = d0 * 0.0625f + btab[bk0];
                d1 = d1 * 0.0625f + btab[bk1];
                d2 = d2 * 0.0625f + btab[bk2];
                d3 = d3 * 0.0625f + btab[bk3];
                if (mk0 == 0) { d0 = -3.402823466e38f; d2 = -3.402823466e38f; }
                if (mk1 == 0) { d1 = -3.402823466e38f; d3 = -3.402823466e38f; }
            }
            float2 o0 = {d0, d1};
            float2 o1 = {d2, d3};
            *(float2*)(C + (long)r0 * N + col) = o0;
            *(float2*)(C + (long)r1 * N + col) = o1;
        }
    }
}

// ---------------------------------------------------------------------------
// Launcher
// ---------------------------------------------------------------------------
extern "C" void kernel_launch(void* const* d_in, const int* in_sizes, int n_in,
                              void* d_out, int out_size)
{
    const float* x    = (const float*)d_in[0];
    const int*   mask = (const int*)  d_in[1];
    const float* btab = (const float*)d_in[2];
    const float* ln_g = (const float*)d_in[3];
    const float* ln_b = (const float*)d_in[4];
    const float* wq   = (const float*)d_in[5];
    const float* bq   = (const float*)d_in[6];
    const float* wk   = (const float*)d_in[7];
    const float* bk   = (const float*)d_in[8];
    const float* wv   = (const float*)d_in[9];
    const float* bv   = (const float*)d_in[10];
    const float* wo   = (const float*)d_in[11];
    const float* bo   = (const float*)d_in[12];
    const float* cmg  = (const float*)d_in[13];
    const float* cmb  = (const float*)d_in[14];
    const float* w1   = (const float*)d_in[15];
    const float* b1   = (const float*)d_in[16];
    const float* w2   = (const float*)d_in[17];
    const float* b2   = (const float*)d_in[18];
    float* xo = (float*)d_out;

    float *H, *Q, *Kb, *V, *O, *T, *Cb, *F, *E;
    cudaGetSymbolAddress((void**)&H,  g_H);
    cudaGetSymbolAddress((void**)&Q,  g_Q);
    cudaGetSymbolAddress((void**)&Kb, g_K);
    cudaGetSymbolAddress((void**)&V,  g_V);
    cudaGetSymbolAddress((void**)&O,  g_O);
    cudaGetSymbolAddress((void**)&T,  g_T);
    cudaGetSymbolAddress((void**)&Cb, g_C);
    cudaGetSymbolAddress((void**)&F,  g_F);
    cudaGetSymbolAddress((void**)&E,  g_E);

    const dim3 blk(256);
    const dim3 gProj(D_ / 128, ROWS / 128, 1);   // (2, 256)
    const dim3 gScore(S_ / 128, S_ / 128, B_);   // (4, 4, 64)
    const dim3 gAV(D_ / 128, S_ / 128, B_);      // (2, 4, 64)
    const int  rowBlocks = ROWS / 8;             // 4096 (8 warps/block)
    const long sQKV = (long)S_ * D_;             // 131072
    const long sE   = (long)S_ * S_;             // 262144

    for (int j = 0; j < 3; j++) {
        const float* xin = (j == 0) ? x : xo;
        const float* gj = ln_g + j * D_;
        const float* bj = ln_b + j * D_;

        // h = LN(x)
        ln_k<<<rowBlocks, 256>>>(xin, nullptr, gj, bj, H, ROWS);

        // q, k, v projections
        gemm_k<1, false><<<gProj, blk>>>(H, wq + j * WSZ, bq + j * D_, nullptr, Q,
                                         ROWS, D_, D_, 0, 0, 0, nullptr, nullptr);
        gemm_k<1, false><<<gProj, blk>>>(H, wk + j * WSZ, bk + j * D_, nullptr, Kb,
                                         ROWS, D_, D_, 0, 0, 0, nullptr, nullptr);
        gemm_k<1, false><<<gProj, blk>>>(H, wv + j * WSZ, bv + j * D_, nullptr, V,
                                         ROWS, D_, D_, 0, 0, 0, nullptr, nullptr);

        // e = q k^T / 16 + relpos_bias, masked
        gemm_k<4, true><<<gScore, blk>>>(Q, Kb, nullptr, nullptr, E,
                                         S_, S_, D_, sQKV, sQKV, sE, mask, btab);

        // a = softmax(e)
        softmax_k<<<rowBlocks, 256>>>(E, ROWS);

        // o = a @ v
        gemm_k<0, false><<<gAV, blk>>>(E, V, nullptr, nullptr, O,
                                       S_, D_, S_, sE, sQKV, sQKV, nullptr, nullptr);

        // t = o @ wo + bo
        gemm_k<1, false><<<gProj, blk>>>(O, wo + j * WSZ, bo + j * D_, nullptr, T,
                                         ROWS, D_, D_, 0, 0, 0, nullptr, nullptr);

        // x = h + LN(t)   (same gamma/beta as the first LN, per source)
        ln_k<<<rowBlocks, 256>>>(T, H, gj, bj, xo, ROWS);

        // c = LN_cm(x)
        ln_k<<<rowBlocks, 256>>>(xo, nullptr, cmg + j * D_, cmb + j * D_, Cb, ROWS);

        // f = gelu(c @ w1 + b1)   (exact gelu)
        gemm_k<2, false><<<gProj, blk>>>(Cb, w1 + j * WSZ, b1 + j * D_, nullptr, F,
                                         ROWS, D_, D_, 0, 0, 0, nullptr, nullptr);

        // x = x + f @ w2 + b2
        gemm_k<3, false><<<gProj, blk>>>(F, w2 + j * WSZ, b2 + j * D_, xo, xo,
                                         ROWS, D_, D_, 0, 0, 0, nullptr, nullptr);
    }
}

// round 5
// speedup vs baseline: 2.9151x; 2.1038x over previous
#include <cuda_runtime.h>
#include <math.h>
#include <stdint.h>

// Problem dims (fixed)
#define B_   64
#define S_   512
#define D_   256
#define ROWS (B_ * S_)          // 32768
#define WSZ  (D_ * D_)          // 65536 per-layer weight size

// ---------------------------------------------------------------------------
// Scratch (device globals; no allocation allowed)
// ---------------------------------------------------------------------------
__device__ float g_H[ROWS * D_];
__device__ float g_Q[ROWS * D_];
__device__ float g_K[ROWS * D_];
__device__ float g_V[ROWS * D_];
__device__ float g_VT[ROWS * D_];
__device__ float g_O[ROWS * D_];
__device__ float g_T[ROWS * D_];
__device__ float g_C[ROWS * D_];
__device__ float g_F[ROWS * D_];
__device__ float g_WT[6 * 3 * WSZ];         // transposed weights
__device__ float g_E[(long)B_ * S_ * S_];   // 64 MB attention scores

// ---------------------------------------------------------------------------
// helpers
// ---------------------------------------------------------------------------
__device__ __forceinline__ uint32_t f2tf(float x) {
    uint32_t r;
    asm("cvt.rna.tf32.f32 %0, %1;" : "=r"(r) : "f"(x));
    return r;
}
__device__ __forceinline__ void mma_tf32(float* d, const uint32_t* a, const uint32_t* b) {
    asm volatile(
        "mma.sync.aligned.m16n8k8.row.col.f32.tf32.tf32.f32 "
        "{%0,%1,%2,%3}, {%4,%5,%6,%7}, {%8,%9}, {%0,%1,%2,%3};"
        : "+f"(d[0]), "+f"(d[1]), "+f"(d[2]), "+f"(d[3])
        : "r"(a[0]), "r"(a[1]), "r"(a[2]), "r"(a[3]), "r"(b[0]), "r"(b[1]));
}

// ---------------------------------------------------------------------------
// Batched 32x32 transpose: out[z][c][r] = in[z][r][c]
// ---------------------------------------------------------------------------
__global__ void tr_k(const float* __restrict__ in, float* __restrict__ out,
                     int rows, int cols)
{
    __shared__ float t[32][33];
    const long bs = (long)rows * cols;
    in  += blockIdx.z * bs;
    out += blockIdx.z * bs;
    const int r0 = blockIdx.y * 32;
    const int c0 = blockIdx.x * 32;
    const int tx = threadIdx.x, ty = threadIdx.y;
    #pragma unroll
    for (int i = 0; i < 32; i += 8)
        t[ty + i][tx] = in[(long)(r0 + ty + i) * cols + c0 + tx];
    __syncthreads();
    #pragma unroll
    for (int i = 0; i < 32; i += 8)
        out[(long)(c0 + ty + i) * rows + r0 + tx] = t[tx][ty + i];
}

// ---------------------------------------------------------------------------
// LayerNorm: one warp per row. out = (res ? res : 0) + LN(in) * g + b
// ---------------------------------------------------------------------------
__global__ void ln_k(const float* __restrict__ in, const float* __restrict__ res,
                     const float* __restrict__ g, const float* __restrict__ b,
                     float* __restrict__ out, int rows)
{
    int warp = (blockIdx.x * blockDim.x + threadIdx.x) >> 5;
    int lane = threadIdx.x & 31;
    if (warp >= rows) return;

    const float4* x4 = (const float4*)(in + (long)warp * D_);
    float4 v0 = x4[lane];
    float4 v1 = x4[lane + 32];

    float s = v0.x + v0.y + v0.z + v0.w + v1.x + v1.y + v1.z + v1.w;
    #pragma unroll
    for (int o = 16; o; o >>= 1) s += __shfl_xor_sync(0xffffffffu, s, o);
    float mean = s * (1.0f / 256.0f);

    float d0x = v0.x - mean, d0y = v0.y - mean, d0z = v0.z - mean, d0w = v0.w - mean;
    float d1x = v1.x - mean, d1y = v1.y - mean, d1z = v1.z - mean, d1w = v1.w - mean;
    float q = d0x*d0x + d0y*d0y + d0z*d0z + d0w*d0w
            + d1x*d1x + d1y*d1y + d1z*d1z + d1w*d1w;
    #pragma unroll
    for (int o = 16; o; o >>= 1) q += __shfl_xor_sync(0xffffffffu, q, o);
    float inv = rsqrtf(q * (1.0f / 256.0f) + 1e-5f);

    const float4* g4 = (const float4*)g;
    const float4* b4 = (const float4*)b;
    float4 gv0 = g4[lane], gv1 = g4[lane + 32];
    float4 bv0 = b4[lane], bv1 = b4[lane + 32];

    float4 o0, o1;
    o0.x = d0x * inv * gv0.x + bv0.x;  o0.y = d0y * inv * gv0.y + bv0.y;
    o0.z = d0z * inv * gv0.z + bv0.z;  o0.w = d0w * inv * gv0.w + bv0.w;
    o1.x = d1x * inv * gv1.x + bv1.x;  o1.y = d1y * inv * gv1.y + bv1.y;
    o1.z = d1z * inv * gv1.z + bv1.z;  o1.w = d1w * inv * gv1.w + bv1.w;

    if (res) {
        const float4* r4 = (const float4*)(res + (long)warp * D_);
        float4 r0 = r4[lane], r1 = r4[lane + 32];
        o0.x += r0.x; o0.y += r0.y; o0.z += r0.z; o0.w += r0.w;
        o1.x += r1.x; o1.y += r1.y; o1.z += r1.z; o1.w += r1.w;
    }

    float4* out4 = (float4*)(out + (long)warp * D_);
    out4[lane]      = o0;
    out4[lane + 32] = o1;
}

// ---------------------------------------------------------------------------
// Softmax over rows of length 512: one warp per row
// ---------------------------------------------------------------------------
__global__ void softmax_k(float* __restrict__ E, int rows)
{
    int warp = (blockIdx.x * blockDim.x + threadIdx.x) >> 5;
    int lane = threadIdx.x & 31;
    if (warp >= rows) return;

    float4* p = (float4*)(E + (long)warp * 512);
    float4 v[4];
    #pragma unroll
    for (int i = 0; i < 4; i++) v[i] = p[lane + 32 * i];

    float mx = -3.402823466e38f;
    #pragma unroll
    for (int i = 0; i < 4; i++)
        mx = fmaxf(mx, fmaxf(fmaxf(v[i].x, v[i].y), fmaxf(v[i].z, v[i].w)));
    #pragma unroll
    for (int o = 16; o; o >>= 1) mx = fmaxf(mx, __shfl_xor_sync(0xffffffffu, mx, o));

    float sum = 0.0f;
    #pragma unroll
    for (int i = 0; i < 4; i++) {
        v[i].x = expf(v[i].x - mx); v[i].y = expf(v[i].y - mx);
        v[i].z = expf(v[i].z - mx); v[i].w = expf(v[i].w - mx);
        sum += v[i].x + v[i].y + v[i].z + v[i].w;
    }
    #pragma unroll
    for (int o = 16; o; o >>= 1) sum += __shfl_xor_sync(0xffffffffu, sum, o);
    float r = 1.0f / sum;

    #pragma unroll
    for (int i = 0; i < 4; i++) {
        v[i].x *= r; v[i].y *= r; v[i].z *= r; v[i].w *= r;
        p[lane + 32 * i] = v[i];
    }
}

// ---------------------------------------------------------------------------
// TF32 mma.sync GEMM 128x128x16, 256 threads (8 warps 2x4), warp 64x32,
// double-buffered, XOR-swizzled row-major smem:
//   word(m, k) = m*16 + (k ^ (((m>>1)&3) << 2))      (128x16-word tile)
// Stores: STS.128 conflict-free. Fragment loads: LDS.32 conflict-free.
// Both A and B sources are [rows][K] row-major (B pre-transposed if needed).
// EPI: 0 none | 1 +bias | 2 gelu(.+bias) | 3 res + (.+bias) | 4 attention score
// ---------------------------------------------------------------------------
template<int EPI>
__global__ void __launch_bounds__(256, 2)
gemm_k(const float* __restrict__ A, const float* __restrict__ Bm,
       const float* __restrict__ bias, const float* __restrict__ res,
       float* __restrict__ C, int M, int N, int K,
       long sA, long sB, long sC,
       const int* __restrict__ mask, const float* __restrict__ btab)
{
    const int tid  = threadIdx.x;
    const int lane = tid & 31;
    const int wm   = (tid >> 5) & 1;    // warp row -> 64 rows
    const int wn   = tid >> 6;          // warp col -> 32 cols
    const int bz   = blockIdx.z;
    A  += (long)bz * sA;
    Bm += (long)bz * sB;
    C  += (long)bz * sC;

    __shared__ uint32_t As[2][2048];
    __shared__ uint32_t Bs[2][2048];

    const int bm = blockIdx.y * 128;
    const int bn = blockIdx.x * 128;

    // ---- staging indices: rows ar, ar+64; k-chunk ac ----
    const int ar = tid >> 2;            // 0..63
    const int ac = (tid & 3) << 2;      // 0,4,8,12
    const int ssw = ((ar >> 1) & 3) << 2;
    const int w0  = ar * 16 + (ac ^ ssw);      // 16B-aligned
    const int w1  = w0 + 1024;                 // row ar+64 (same swizzle)

    // ---- fragment indices ----
    const int g  = lane >> 2;
    const int c  = lane & 3;
    const int e4 = ((g >> 1) & 3) << 2;
    const int fbase = g * 16 + c;

    const float* Ap0 = A + (long)(bm + ar) * K + ac;
    const float* Ap1 = A + (long)(bm + ar + 64) * K + ac;
    const float* Bp0 = Bm + (long)(bn + ar) * K + ac;
    const float* Bp1 = Bm + (long)(bn + ar + 64) * K + ac;

    float acc[4][4][4];
    #pragma unroll
    for (int i = 0; i < 4; i++)
        #pragma unroll
        for (int j = 0; j < 4; j++)
            #pragma unroll
            for (int r = 0; r < 4; r++) acc[i][j][r] = 0.0f;

    // ---- prologue: stage tile 0 ----
    {
        float4 a0 = *(const float4*)Ap0;
        float4 a1 = *(const float4*)Ap1;
        float4 b0 = *(const float4*)Bp0;
        float4 b1 = *(const float4*)Bp1;
        uint4 ta0 = { f2tf(a0.x), f2tf(a0.y), f2tf(a0.z), f2tf(a0.w) };
        uint4 ta1 = { f2tf(a1.x), f2tf(a1.y), f2tf(a1.z), f2tf(a1.w) };
        uint4 tb0 = { f2tf(b0.x), f2tf(b0.y), f2tf(b0.z), f2tf(b0.w) };
        uint4 tb1 = { f2tf(b1.x), f2tf(b1.y), f2tf(b1.z), f2tf(b1.w) };
        *(uint4*)&As[0][w0] = ta0;  *(uint4*)&As[0][w1] = ta1;
        *(uint4*)&Bs[0][w0] = tb0;  *(uint4*)&Bs[0][w1] = tb1;
    }
    __syncthreads();

    int buf = 0;
    for (int k0 = 0; k0 < K; k0 += 16) {
        const int knext = k0 + 16;
        const bool more = (knext < K);
        float4 a0, a1, b0, b1;
        if (more) {
            a0 = *(const float4*)(Ap0 + knext);
            a1 = *(const float4*)(Ap1 + knext);
            b0 = *(const float4*)(Bp0 + knext);
            b1 = *(const float4*)(Bp1 + knext);
        }

        const uint32_t* Ab = As[buf];
        const uint32_t* Bb = Bs[buf];
        #pragma unroll
        for (int kb = 0; kb < 2; kb++) {
            const int xa = (kb * 8) ^ e4;          // k-regs 0/1
            const int xb = (kb * 8 + 4) ^ e4;      // k-regs 2/3
            uint32_t af[4][4];
            uint32_t bf[4][2];
            #pragma unroll
            for (int ma = 0; ma < 4; ma++) {
                const int mb = (wm * 64 + ma * 16) * 16 + fbase;
                af[ma][0] = Ab[mb + xa];
                af[ma][1] = Ab[mb + 128 + xa];
                af[ma][2] = Ab[mb + xb];
                af[ma][3] = Ab[mb + 128 + xb];
            }
            #pragma unroll
            for (int nb = 0; nb < 4; nb++) {
                const int nbm = (wn * 32 + nb * 8) * 16 + fbase;
                bf[nb][0] = Bb[nbm + xa];
                bf[nb][1] = Bb[nbm + xb];
            }
            #pragma unroll
            for (int ma = 0; ma < 4; ma++)
                #pragma unroll
                for (int nb = 0; nb < 4; nb++)
                    mma_tf32(acc[ma][nb], af[ma], bf[nb]);
        }

        if (!more) break;
        const int nbuf = buf ^ 1;
        uint4 ta0 = { f2tf(a0.x), f2tf(a0.y), f2tf(a0.z), f2tf(a0.w) };
        uint4 ta1 = { f2tf(a1.x), f2tf(a1.y), f2tf(a1.z), f2tf(a1.w) };
        uint4 tb0 = { f2tf(b0.x), f2tf(b0.y), f2tf(b0.z), f2tf(b0.w) };
        uint4 tb1 = { f2tf(b1.x), f2tf(b1.y), f2tf(b1.z), f2tf(b1.w) };
        *(uint4*)&As[nbuf][w0] = ta0;  *(uint4*)&As[nbuf][w1] = ta1;
        *(uint4*)&Bs[nbuf][w0] = tb0;  *(uint4*)&Bs[nbuf][w1] = tb1;
        __syncthreads();
        buf = nbuf;
    }

    // ---- epilogue ----
    #pragma unroll
    for (int nb = 0; nb < 4; nb++) {
        const int col = bn + wn * 32 + nb * 8 + c * 2;

        float2 bias2 = {0.0f, 0.0f};
        if (EPI == 1 || EPI == 2 || EPI == 3)
            bias2 = *(const float2*)(bias + col);
        int mk0 = 0, mk1 = 0;
        if (EPI == 4) {
            mk0 = mask[bz * S_ + col];
            mk1 = mask[bz * S_ + col + 1];
        }

        #pragma unroll
        for (int ma = 0; ma < 4; ma++) {
            const int r0 = bm + wm * 64 + ma * 16 + g;
            const int r1 = r0 + 8;
            float d0 = acc[ma][nb][0], d1 = acc[ma][nb][1];
            float d2 = acc[ma][nb][2], d3 = acc[ma][nb][3];

            if (EPI == 1 || EPI == 2 || EPI == 3) {
                d0 += bias2.x; d1 += bias2.y;
                d2 += bias2.x; d3 += bias2.y;
            }
            if (EPI == 2) {
                d0 = 0.5f * d0 * (1.0f + erff(d0 * 0.70710678118654752f));
                d1 = 0.5f * d1 * (1.0f + erff(d1 * 0.70710678118654752f));
                d2 = 0.5f * d2 * (1.0f + erff(d2 * 0.70710678118654752f));
                d3 = 0.5f * d3 * (1.0f + erff(d3 * 0.70710678118654752f));
            }
            if (EPI == 3) {
                float2 ra = *(const float2*)(res + (long)r0 * N + col);
                float2 rb = *(const float2*)(res + (long)r1 * N + col);
                d0 += ra.x; d1 += ra.y; d2 += rb.x; d3 += rb.y;
            }
            if (EPI == 4) {
                int rel0 = col - r0;
                int rel1 = col + 1 - r0;
                int rel2 = col - r1;
                int rel3 = col + 1 - r1;
                int bk0 = (rel0 < 0) ? (511 - rel0) : rel0;
                int bk1 = (rel1 < 0) ? (511 - rel1) : rel1;
                int bk2 = (rel2 < 0) ? (511 - rel2) : rel2;
                int bk3 = (rel3 < 0) ? (511 - rel3) : rel3;
                d0 = d0 * 0.0625f + btab[bk0];
                d1 = d1 * 0.0625f + btab[bk1];
                d2 = d2 * 0.0625f + btab[bk2];
                d3 = d3 * 0.0625f + btab[bk3];
                if (mk0 == 0) { d0 = -3.402823466e38f; d2 = -3.402823466e38f; }
                if (mk1 == 0) { d1 = -3.402823466e38f; d3 = -3.402823466e38f; }
            }
            float2 o0 = {d0, d1};
            float2 o1 = {d2, d3};
            *(float2*)(C + (long)r0 * N + col) = o0;
            *(float2*)(C + (long)r1 * N + col) = o1;
        }
    }
}

// ---------------------------------------------------------------------------
// Launcher
// ---------------------------------------------------------------------------
extern "C" void kernel_launch(void* const* d_in, const int* in_sizes, int n_in,
                              void* d_out, int out_size)
{
    const float* x    = (const float*)d_in[0];
    const int*   mask = (const int*)  d_in[1];
    const float* btab = (const float*)d_in[2];
    const float* ln_g = (const float*)d_in[3];
    const float* ln_b = (const float*)d_in[4];
    const float* wq   = (const float*)d_in[5];
    const float* bq   = (const float*)d_in[6];
    const float* wk   = (const float*)d_in[7];
    const float* bk   = (const float*)d_in[8];
    const float* wv   = (const float*)d_in[9];
    const float* bv   = (const float*)d_in[10];
    const float* wo   = (const float*)d_in[11];
    const float* bo   = (const float*)d_in[12];
    const float* cmg  = (const float*)d_in[13];
    const float* cmb  = (const float*)d_in[14];
    const float* w1   = (const float*)d_in[15];
    const float* b1   = (const float*)d_in[16];
    const float* w2   = (const float*)d_in[17];
    const float* b2   = (const float*)d_in[18];
    float* xo = (float*)d_out;

    float *H, *Q, *Kb, *V, *VT, *O, *T, *Cb, *F, *E, *WT;
    cudaGetSymbolAddress((void**)&H,  g_H);
    cudaGetSymbolAddress((void**)&Q,  g_Q);
    cudaGetSymbolAddress((void**)&Kb, g_K);
    cudaGetSymbolAddress((void**)&V,  g_V);
    cudaGetSymbolAddress((void**)&VT, g_VT);
    cudaGetSymbolAddress((void**)&O,  g_O);
    cudaGetSymbolAddress((void**)&T,  g_T);
    cudaGetSymbolAddress((void**)&Cb, g_C);
    cudaGetSymbolAddress((void**)&F,  g_F);
    cudaGetSymbolAddress((void**)&E,  g_E);
    cudaGetSymbolAddress((void**)&WT, g_WT);

    // one-time (per launch) weight transposes: WT[w][layer] = w^T
    const dim3 trW(8, 8, 3), trB(32, 8);
    tr_k<<<trW, trB>>>(wq, WT + 0L * 3 * WSZ, D_, D_);
    tr_k<<<trW, trB>>>(wk, WT + 1L * 3 * WSZ, D_, D_);
    tr_k<<<trW, trB>>>(wv, WT + 2L * 3 * WSZ, D_, D_);
    tr_k<<<trW, trB>>>(wo, WT + 3L * 3 * WSZ, D_, D_);
    tr_k<<<trW, trB>>>(w1, WT + 4L * 3 * WSZ, D_, D_);
    tr_k<<<trW, trB>>>(w2, WT + 5L * 3 * WSZ, D_, D_);

    const dim3 blk(256);
    const dim3 gProj(D_ / 128, ROWS / 128, 1);   // (2, 256)
    const dim3 gScore(S_ / 128, S_ / 128, B_);   // (4, 4, 64)
    const dim3 gAV(D_ / 128, S_ / 128, B_);      // (2, 4, 64)
    const dim3 gTrV(D_ / 32, S_ / 32, B_);       // (8, 16, 64)
    const int  rowBlocks = ROWS / 8;             // 4096
    const long sQKV = (long)S_ * D_;             // 131072
    const long sE   = (long)S_ * S_;             // 262144

    for (int j = 0; j < 3; j++) {
        const float* xin = (j == 0) ? x : xo;
        const float* gj = ln_g + j * D_;
        const float* bj = ln_b + j * D_;
        const float* wqT = WT + (0L * 3 + j) * WSZ;
        const float* wkT = WT + (1L * 3 + j) * WSZ;
        const float* wvT = WT + (2L * 3 + j) * WSZ;
        const float* woT = WT + (3L * 3 + j) * WSZ;
        const float* w1T = WT + (4L * 3 + j) * WSZ;
        const float* w2T = WT + (5L * 3 + j) * WSZ;

        // h = LN(x)
        ln_k<<<rowBlocks, 256>>>(xin, nullptr, gj, bj, H, ROWS);

        // q, k, v projections (B = W^T, [N][K] row-major)
        gemm_k<1><<<gProj, blk>>>(H, wqT, bq + j * D_, nullptr, Q,
                                  ROWS, D_, D_, 0, 0, 0, nullptr, nullptr);
        gemm_k<1><<<gProj, blk>>>(H, wkT, bk + j * D_, nullptr, Kb,
                                  ROWS, D_, D_, 0, 0, 0, nullptr, nullptr);
        gemm_k<1><<<gProj, blk>>>(H, wvT, bv + j * D_, nullptr, V,
                                  ROWS, D_, D_, 0, 0, 0, nullptr, nullptr);

        // V^T per batch: [b][d][s]
        tr_k<<<gTrV, trB>>>(V, VT, S_, D_);

        // e = q k^T / 16 + relpos_bias, masked (B = Kmat, naturally [n][k])
        gemm_k<4><<<gScore, blk>>>(Q, Kb, nullptr, nullptr, E,
                                   S_, S_, D_, sQKV, sQKV, sE, mask, btab);

        // a = softmax(e)
        softmax_k<<<rowBlocks, 256>>>(E, ROWS);

        // o = a @ v (B = V^T, [d][s] per batch)
        gemm_k<0><<<gAV, blk>>>(E, VT, nullptr, nullptr, O,
                                S_, D_, S_, sE, sQKV, sQKV, nullptr, nullptr);

        // t = o @ wo + bo
        gemm_k<1><<<gProj, blk>>>(O, woT, bo + j * D_, nullptr, T,
                                  ROWS, D_, D_, 0, 0, 0, nullptr, nullptr);

        // x = h + LN(t)
        ln_k<<<rowBlocks, 256>>>(T, H, gj, bj, xo, ROWS);

        // c = LN_cm(x)
        ln_k<<<rowBlocks, 256>>>(xo, nullptr, cmg + j * D_, cmb + j * D_, Cb, ROWS);

        // f = gelu(c @ w1 + b1)
        gemm_k<2><<<gProj, blk>>>(Cb, w1T, b1 + j * D_, nullptr, F,
                                  ROWS, D_, D_, 0, 0, 0, nullptr, nullptr);

        // x = x + f @ w2 + b2
        gemm_k<3><<<gProj, blk>>>(F, w2T, b2 + j * D_, xo, xo,
                                  ROWS, D_, D_, 0, 0, 0, nullptr, nullptr);
    }
}

// round 6
// speedup vs baseline: 3.4890x; 1.1969x over previous
#include <cuda_runtime.h>
#include <math.h>
#include <stdint.h>

// Problem dims (fixed)
#define B_   64
#define S_   512
#define D_   256
#define ROWS (B_ * S_)          // 32768
#define WSZ  (D_ * D_)          // 65536 per-layer weight size

// ---------------------------------------------------------------------------
// Scratch (device globals; no allocation allowed)
// ---------------------------------------------------------------------------
__device__ float g_H[ROWS * D_];
__device__ float g_Q[ROWS * D_];
__device__ float g_K[ROWS * D_];
__device__ float g_V[ROWS * D_];
__device__ float g_VT[ROWS * D_];
__device__ float g_O[ROWS * D_];
__device__ float g_T[ROWS * D_];
__device__ float g_C[ROWS * D_];
__device__ float g_F[ROWS * D_];
__device__ float g_WT[6 * 3 * WSZ];         // transposed weights
__device__ float g_E[(long)B_ * S_ * S_];   // 64 MB attention scores

// ---------------------------------------------------------------------------
// helpers
// ---------------------------------------------------------------------------
__device__ __forceinline__ uint32_t smem_u32(const void* p) {
    uint32_t a;
    asm("{ .reg .u64 t; cvta.to.shared.u64 t, %1; cvt.u32.u64 %0, t; }"
        : "=r"(a) : "l"(p));
    return a;
}
__device__ __forceinline__ uint32_t f2tf(float x) {
    uint32_t r;
    asm("cvt.rna.tf32.f32 %0, %1;" : "=r"(r) : "f"(x));
    return r;
}
__device__ __forceinline__ void mma_tf32(float* d, const uint32_t* a, const uint32_t* b) {
    asm volatile(
        "mma.sync.aligned.m16n8k8.row.col.f32.tf32.tf32.f32 "
        "{%0,%1,%2,%3}, {%4,%5,%6,%7}, {%8,%9}, {%0,%1,%2,%3};"
        : "+f"(d[0]), "+f"(d[1]), "+f"(d[2]), "+f"(d[3])
        : "r"(a[0]), "r"(a[1]), "r"(a[2]), "r"(a[3]), "r"(b[0]), "r"(b[1]));
}
__device__ __forceinline__ void cp16(uint32_t dst, const void* src) {
    asm volatile("cp.async.cg.shared.global [%0], [%1], 16;"
                 :: "r"(dst), "l"(src) : "memory");
}
__device__ __forceinline__ void cp_commit() {
    asm volatile("cp.async.commit_group;" ::: "memory");
}

// ---------------------------------------------------------------------------
// Batched 32x32 transpose: out[z][c][r] = in[z][r][c]
// ---------------------------------------------------------------------------
__global__ void tr_k(const float* __restrict__ in, float* __restrict__ out,
                     int rows, int cols)
{
    __shared__ float t[32][33];
    const long bs = (long)rows * cols;
    in  += blockIdx.z * bs;
    out += blockIdx.z * bs;
    const int r0 = blockIdx.y * 32;
    const int c0 = blockIdx.x * 32;
    const int tx = threadIdx.x, ty = threadIdx.y;
    #pragma unroll
    for (int i = 0; i < 32; i += 8)
        t[ty + i][tx] = in[(long)(r0 + ty + i) * cols + c0 + tx];
    __syncthreads();
    #pragma unroll
    for (int i = 0; i < 32; i += 8)
        out[(long)(c0 + ty + i) * rows + r0 + tx] = t[tx][ty + i];
}

// ---------------------------------------------------------------------------
// LayerNorm: one warp per row. out = (res ? res : 0) + LN(in) * g + b
// ---------------------------------------------------------------------------
__global__ void ln_k(const float* __restrict__ in, const float* __restrict__ res,
                     const float* __restrict__ g, const float* __restrict__ b,
                     float* __restrict__ out, int rows)
{
    int warp = (blockIdx.x * blockDim.x + threadIdx.x) >> 5;
    int lane = threadIdx.x & 31;
    if (warp >= rows) return;

    const float4* x4 = (const float4*)(in + (long)warp * D_);
    float4 v0 = x4[lane];
    float4 v1 = x4[lane + 32];

    float s = v0.x + v0.y + v0.z + v0.w + v1.x + v1.y + v1.z + v1.w;
    #pragma unroll
    for (int o = 16; o; o >>= 1) s += __shfl_xor_sync(0xffffffffu, s, o);
    float mean = s * (1.0f / 256.0f);

    float d0x = v0.x - mean, d0y = v0.y - mean, d0z = v0.z - mean, d0w = v0.w - mean;
    float d1x = v1.x - mean, d1y = v1.y - mean, d1z = v1.z - mean, d1w = v1.w - mean;
    float q = d0x*d0x + d0y*d0y + d0z*d0z + d0w*d0w
            + d1x*d1x + d1y*d1y + d1z*d1z + d1w*d1w;
    #pragma unroll
    for (int o = 16; o; o >>= 1) q += __shfl_xor_sync(0xffffffffu, q, o);
    float inv = rsqrtf(q * (1.0f / 256.0f) + 1e-5f);

    const float4* g4 = (const float4*)g;
    const float4* b4 = (const float4*)b;
    float4 gv0 = g4[lane], gv1 = g4[lane + 32];
    float4 bv0 = b4[lane], bv1 = b4[lane + 32];

    float4 o0, o1;
    o0.x = d0x * inv * gv0.x + bv0.x;  o0.y = d0y * inv * gv0.y + bv0.y;
    o0.z = d0z * inv * gv0.z + bv0.z;  o0.w = d0w * inv * gv0.w + bv0.w;
    o1.x = d1x * inv * gv1.x + bv1.x;  o1.y = d1y * inv * gv1.y + bv1.y;
    o1.z = d1z * inv * gv1.z + bv1.z;  o1.w = d1w * inv * gv1.w + bv1.w;

    if (res) {
        const float4* r4 = (const float4*)(res + (long)warp * D_);
        float4 r0 = r4[lane], r1 = r4[lane + 32];
        o0.x += r0.x; o0.y += r0.y; o0.z += r0.z; o0.w += r0.w;
        o1.x += r1.x; o1.y += r1.y; o1.z += r1.z; o1.w += r1.w;
    }

    float4* out4 = (float4*)(out + (long)warp * D_);
    out4[lane]      = o0;
    out4[lane + 32] = o1;
}

// ---------------------------------------------------------------------------
// Softmax over rows of length 512: one warp per row
// ---------------------------------------------------------------------------
__global__ void softmax_k(float* __restrict__ E, int rows)
{
    int warp = (blockIdx.x * blockDim.x + threadIdx.x) >> 5;
    int lane = threadIdx.x & 31;
    if (warp >= rows) return;

    float4* p = (float4*)(E + (long)warp * 512);
    float4 v[4];
    #pragma unroll
    for (int i = 0; i < 4; i++) v[i] = p[lane + 32 * i];

    float mx = -3.402823466e38f;
    #pragma unroll
    for (int i = 0; i < 4; i++)
        mx = fmaxf(mx, fmaxf(fmaxf(v[i].x, v[i].y), fmaxf(v[i].z, v[i].w)));
    #pragma unroll
    for (int o = 16; o; o >>= 1) mx = fmaxf(mx, __shfl_xor_sync(0xffffffffu, mx, o));

    float sum = 0.0f;
    #pragma unroll
    for (int i = 0; i < 4; i++) {
        v[i].x = expf(v[i].x - mx); v[i].y = expf(v[i].y - mx);
        v[i].z = expf(v[i].z - mx); v[i].w = expf(v[i].w - mx);
        sum += v[i].x + v[i].y + v[i].z + v[i].w;
    }
    #pragma unroll
    for (int o = 16; o; o >>= 1) sum += __shfl_xor_sync(0xffffffffu, sum, o);
    float r = 1.0f / sum;

    #pragma unroll
    for (int i = 0; i < 4; i++) {
        v[i].x *= r; v[i].y *= r; v[i].z *= r; v[i].w *= r;
        p[lane + 32 * i] = v[i];
    }
}

// ---------------------------------------------------------------------------
// TF32 mma.sync GEMM 128x128x16: 128 threads (4 warps 2x2), warp tile 64x64,
// cp.async double-buffered, XOR-swizzled row-major smem (raw f32, cvt at
// fragment load):  word(m, k) = m*16 + (k ^ (((m>>1)&3) << 2))
// Both A and B sources are [rows][K] row-major (B pre-transposed if needed).
// EPI: 0 none | 1 +bias | 2 gelu(.+bias) | 3 res + (.+bias) | 4 attention score
// ---------------------------------------------------------------------------
template<int EPI>
__global__ void __launch_bounds__(128, 2)
gemm_k(const float* __restrict__ A, const float* __restrict__ Bm,
       const float* __restrict__ bias, const float* __restrict__ res,
       float* __restrict__ C, int M, int N, int K,
       long sA, long sB, long sC,
       const int* __restrict__ mask, const float* __restrict__ btab)
{
    const int tid  = threadIdx.x;
    const int lane = tid & 31;
    const int wm   = (tid >> 5) & 1;    // warp row -> 64 rows
    const int wn   = tid >> 6;          // warp col -> 64 cols
    const int bz   = blockIdx.z;
    A  += (long)bz * sA;
    Bm += (long)bz * sB;
    C  += (long)bz * sC;

    __shared__ float As[2][2048];
    __shared__ float Bs[2][2048];

    const int bm = blockIdx.y * 128;
    const int bn = blockIdx.x * 128;

    // ---- staging indices: thread covers rows sr+32j (j=0..3), chunk sc ----
    const int sr  = tid >> 2;            // 0..31
    const int sc  = (tid & 3) << 2;      // 0,4,8,12
    const int ssw = ((sr >> 1) & 3) << 2;
    const int w0  = sr * 16 + (sc ^ ssw);       // +512 per j

    const uint32_t sAu = smem_u32(&As[0][0]);
    const uint32_t sBu = smem_u32(&Bs[0][0]);

    const float* Ap[4];
    const float* Bp[4];
    #pragma unroll
    for (int j = 0; j < 4; j++) {
        Ap[j] = A  + (long)(bm + sr + 32 * j) * K + sc;
        Bp[j] = Bm + (long)(bn + sr + 32 * j) * K + sc;
    }

    // ---- fragment indices ----
    const int g  = lane >> 2;
    const int c  = lane & 3;
    const int e4 = ((g >> 1) & 3) << 2;
    const int fbase = g * 16 + c;

    float acc[4][8][4];
    #pragma unroll
    for (int i = 0; i < 4; i++)
        #pragma unroll
        for (int j = 0; j < 8; j++)
            #pragma unroll
            for (int r = 0; r < 4; r++) acc[i][j][r] = 0.0f;

    const int nst = K >> 4;

    // ---- prologue: async-stage tile 0 into buf 0 ----
    #pragma unroll
    for (int j = 0; j < 4; j++) {
        cp16(sAu + (w0 + 512 * j) * 4, Ap[j]);
        cp16(sBu + (w0 + 512 * j) * 4, Bp[j]);
    }
    cp_commit();

    int buf = 0;
    for (int s = 0; s < nst; s++) {
        const bool more = (s + 1 < nst);
        if (more) {
            const int kn = (s + 1) << 4;
            const uint32_t dA = sAu + (8192 * (buf ^ 1)) + w0 * 4;
            const uint32_t dB = sBu + (8192 * (buf ^ 1)) + w0 * 4;
            #pragma unroll
            for (int j = 0; j < 4; j++) {
                cp16(dA + 2048 * j, Ap[j] + kn);
                cp16(dB + 2048 * j, Bp[j] + kn);
            }
            cp_commit();
            asm volatile("cp.async.wait_group 1;" ::: "memory");
        } else {
            asm volatile("cp.async.wait_group 0;" ::: "memory");
        }
        __syncthreads();

        const float* Ab = As[buf];
        const float* Bb = Bs[buf];
        #pragma unroll
        for (int kb = 0; kb < 2; kb++) {
            const int xa = (kb * 8) ^ e4;
            const int xb = (kb * 8 + 4) ^ e4;
            uint32_t af[4][4];
            uint32_t bf[8][2];
            #pragma unroll
            for (int ma = 0; ma < 4; ma++) {
                const int mb = (wm * 64 + ma * 16) * 16 + fbase;
                af[ma][0] = f2tf(Ab[mb + xa]);
                af[ma][1] = f2tf(Ab[mb + 128 + xa]);
                af[ma][2] = f2tf(Ab[mb + xb]);
                af[ma][3] = f2tf(Ab[mb + 128 + xb]);
            }
            #pragma unroll
            for (int nb = 0; nb < 8; nb++) {
                const int nbm = (wn * 64 + nb * 8) * 16 + fbase;
                bf[nb][0] = f2tf(Bb[nbm + xa]);
                bf[nb][1] = f2tf(Bb[nbm + xb]);
            }
            #pragma unroll
            for (int ma = 0; ma < 4; ma++)
                #pragma unroll
                for (int nb = 0; nb < 8; nb++)
                    mma_tf32(acc[ma][nb], af[ma], bf[nb]);
        }
        __syncthreads();        // all reads of buf done before s+2 overwrites it
        buf ^= 1;
    }

    // ---- epilogue ----
    #pragma unroll
    for (int nb = 0; nb < 8; nb++) {
        const int col = bn + wn * 64 + nb * 8 + c * 2;

        float2 bias2 = {0.0f, 0.0f};
        if (EPI == 1 || EPI == 2 || EPI == 3)
            bias2 = *(const float2*)(bias + col);
        int mk0 = 0, mk1 = 0;
        if (EPI == 4) {
            mk0 = mask[bz * S_ + col];
            mk1 = mask[bz * S_ + col + 1];
        }

        #pragma unroll
        for (int ma = 0; ma < 4; ma++) {
            const int r0 = bm + wm * 64 + ma * 16 + g;
            const int r1 = r0 + 8;
            float d0 = acc[ma][nb][0], d1 = acc[ma][nb][1];
            float d2 = acc[ma][nb][2], d3 = acc[ma][nb][3];

            if (EPI == 1 || EPI == 2 || EPI == 3) {
                d0 += bias2.x; d1 += bias2.y;
                d2 += bias2.x; d3 += bias2.y;
            }
            if (EPI == 2) {
                d0 = 0.5f * d0 * (1.0f + erff(d0 * 0.70710678118654752f));
                d1 = 0.5f * d1 * (1.0f + erff(d1 * 0.70710678118654752f));
                d2 = 0.5f * d2 * (1.0f + erff(d2 * 0.70710678118654752f));
                d3 = 0.5f * d3 * (1.0f + erff(d3 * 0.70710678118654752f));
            }
            if (EPI == 3) {
                float2 ra = *(const float2*)(res + (long)r0 * N + col);
                float2 rb = *(const float2*)(res + (long)r1 * N + col);
                d0 += ra.x; d1 += ra.y; d2 += rb.x; d3 += rb.y;
            }
            if (EPI == 4) {
                int rel0 = col - r0;
                int rel1 = col + 1 - r0;
                int rel2 = col - r1;
                int rel3 = col + 1 - r1;
                int bk0 = (rel0 < 0) ? (511 - rel0) : rel0;
                int bk1 = (rel1 < 0) ? (511 - rel1) : rel1;
                int bk2 = (rel2 < 0) ? (511 - rel2) : rel2;
                int bk3 = (rel3 < 0) ? (511 - rel3) : rel3;
                d0 = d0 * 0.0625f + btab[bk0];
                d1 = d1 * 0.0625f + btab[bk1];
                d2 = d2 * 0.0625f + btab[bk2];
                d3 = d3 * 0.0625f + btab[bk3];
                if (mk0 == 0) { d0 = -3.402823466e38f; d2 = -3.402823466e38f; }
                if (mk1 == 0) { d1 = -3.402823466e38f; d3 = -3.402823466e38f; }
            }
            float2 o0 = {d0, d1};
            float2 o1 = {d2, d3};
            *(float2*)(C + (long)r0 * N + col) = o0;
            *(float2*)(C + (long)r1 * N + col) = o1;
        }
    }
}

// ---------------------------------------------------------------------------
// Launcher
// ---------------------------------------------------------------------------
extern "C" void kernel_launch(void* const* d_in, const int* in_sizes, int n_in,
                              void* d_out, int out_size)
{
    const float* x    = (const float*)d_in[0];
    const int*   mask = (const int*)  d_in[1];
    const float* btab = (const float*)d_in[2];
    const float* ln_g = (const float*)d_in[3];
    const float* ln_b = (const float*)d_in[4];
    const float* wq   = (const float*)d_in[5];
    const float* bq   = (const float*)d_in[6];
    const float* wk   = (const float*)d_in[7];
    const float* bk   = (const float*)d_in[8];
    const float* wv   = (const float*)d_in[9];
    const float* bv   = (const float*)d_in[10];
    const float* wo   = (const float*)d_in[11];
    const float* bo   = (const float*)d_in[12];
    const float* cmg  = (const float*)d_in[13];
    const float* cmb  = (const float*)d_in[14];
    const float* w1   = (const float*)d_in[15];
    const float* b1   = (const float*)d_in[16];
    const float* w2   = (const float*)d_in[17];
    const float* b2   = (const float*)d_in[18];
    float* xo = (float*)d_out;

    float *H, *Q, *Kb, *V, *VT, *O, *T, *Cb, *F, *E, *WT;
    cudaGetSymbolAddress((void**)&H,  g_H);
    cudaGetSymbolAddress((void**)&Q,  g_Q);
    cudaGetSymbolAddress((void**)&Kb, g_K);
    cudaGetSymbolAddress((void**)&V,  g_V);
    cudaGetSymbolAddress((void**)&VT, g_VT);
    cudaGetSymbolAddress((void**)&O,  g_O);
    cudaGetSymbolAddress((void**)&T,  g_T);
    cudaGetSymbolAddress((void**)&Cb, g_C);
    cudaGetSymbolAddress((void**)&F,  g_F);
    cudaGetSymbolAddress((void**)&E,  g_E);
    cudaGetSymbolAddress((void**)&WT, g_WT);

    // one-time (per launch) weight transposes: WT[w][layer] = w^T
    const dim3 trW(8, 8, 3), trB(32, 8);
    tr_k<<<trW, trB>>>(wq, WT + 0L * 3 * WSZ, D_, D_);
    tr_k<<<trW, trB>>>(wk, WT + 1L * 3 * WSZ, D_, D_);
    tr_k<<<trW, trB>>>(wv, WT + 2L * 3 * WSZ, D_, D_);
    tr_k<<<trW, trB>>>(wo, WT + 3L * 3 * WSZ, D_, D_);
    tr_k<<<trW, trB>>>(w1, WT + 4L * 3 * WSZ, D_, D_);
    tr_k<<<trW, trB>>>(w2, WT + 5L * 3 * WSZ, D_, D_);

    const dim3 blk(128);
    const dim3 gProj(D_ / 128, ROWS / 128, 1);   // (2, 256)
    const dim3 gScore(S_ / 128, S_ / 128, B_);   // (4, 4, 64)
    const dim3 gAV(D_ / 128, S_ / 128, B_);      // (2, 4, 64)
    const dim3 gTrV(D_ / 32, S_ / 32, B_);       // (8, 16, 64)
    const int  rowBlocks = ROWS / 8;             // 4096
    const long sQKV = (long)S_ * D_;             // 131072
    const long sE   = (long)S_ * S_;             // 262144

    for (int j = 0; j < 3; j++) {
        const float* xin = (j == 0) ? x : xo;
        const float* gj = ln_g + j * D_;
        const float* bj = ln_b + j * D_;
        const float* wqT = WT + (0L * 3 + j) * WSZ;
        const float* wkT = WT + (1L * 3 + j) * WSZ;
        const float* wvT = WT + (2L * 3 + j) * WSZ;
        const float* woT = WT + (3L * 3 + j) * WSZ;
        const float* w1T = WT + (4L * 3 + j) * WSZ;
        const float* w2T = WT + (5L * 3 + j) * WSZ;

        // h = LN(x)
        ln_k<<<rowBlocks, 256>>>(xin, nullptr, gj, bj, H, ROWS);

        // q, k, v projections (B = W^T, [N][K] row-major)
        gemm_k<1><<<gProj, blk>>>(H, wqT, bq + j * D_, nullptr, Q,
                                  ROWS, D_, D_, 0, 0, 0, nullptr, nullptr);
        gemm_k<1><<<gProj, blk>>>(H, wkT, bk + j * D_, nullptr, Kb,
                                  ROWS, D_, D_, 0, 0, 0, nullptr, nullptr);
        gemm_k<1><<<gProj, blk>>>(H, wvT, bv + j * D_, nullptr, V,
                                  ROWS, D_, D_, 0, 0, 0, nullptr, nullptr);

        // V^T per batch: [b][d][s]
        tr_k<<<gTrV, trB>>>(V, VT, S_, D_);

        // e = q k^T / 16 + relpos_bias, masked (B = Kmat, naturally [n][k])
        gemm_k<4><<<gScore, blk>>>(Q, Kb, nullptr, nullptr, E,
                                   S_, S_, D_, sQKV, sQKV, sE, mask, btab);

        // a = softmax(e)
        softmax_k<<<rowBlocks, 256>>>(E, ROWS);

        // o = a @ v (B = V^T, [d][s] per batch)
        gemm_k<0><<<gAV, blk>>>(E, VT, nullptr, nullptr, O,
                                S_, D_, S_, sE, sQKV, sQKV, nullptr, nullptr);

        // t = o @ wo + bo
        gemm_k<1><<<gProj, blk>>>(O, woT, bo + j * D_, nullptr, T,
                                  ROWS, D_, D_, 0, 0, 0, nullptr, nullptr);

        // x = h + LN(t)
        ln_k<<<rowBlocks, 256>>>(T, H, gj, bj, xo, ROWS);

        // c = LN_cm(x)
        ln_k<<<rowBlocks, 256>>>(xo, nullptr, cmg + j * D_, cmb + j * D_, Cb, ROWS);

        // f = gelu(c @ w1 + b1)
        gemm_k<2><<<gProj, blk>>>(Cb, w1T, b1 + j * D_, nullptr, F,
                                  ROWS, D_, D_, 0, 0, 0, nullptr, nullptr);

        // x = x + f @ w2 + b2
        gemm_k<3><<<gProj, blk>>>(F, w2T, b2 + j * D_, xo, xo,
                                  ROWS, D_, D_, 0, 0, 0, nullptr, nullptr);
    }
}

// round 7
// speedup vs baseline: 3.7788x; 1.0831x over previous
#include <cuda_runtime.h>
#include <cuda_fp16.h>
#include <math.h>
#include <stdint.h>

// Problem dims (fixed)
#define B_   64
#define S_   512
#define D_   256
#define ROWS (B_ * S_)          // 32768
#define WSZ  (D_ * D_)          // 65536 per-layer weight size

// ---------------------------------------------------------------------------
// Scratch (device globals; no allocation allowed)
// ---------------------------------------------------------------------------
__device__ __half g_H16[ROWS * D_];
__device__ __half g_Q16[ROWS * D_];
__device__ __half g_K16[ROWS * D_];
__device__ __half g_V16[ROWS * D_];
__device__ __half g_VT16[ROWS * D_];
__device__ __half g_O16[ROWS * D_];
__device__ __half g_C16[ROWS * D_];
__device__ __half g_F16[ROWS * D_];
__device__ __half g_WT16[6 * 3 * WSZ];        // transposed fp16 weights
__device__ __half g_P16[(long)B_ * S_ * S_];  // softmax probs (fp16)
__device__ float  g_H32[ROWS * D_];           // LN(x) fp32 (residual use)
__device__ float  g_T32[ROWS * D_];           // attn-out pre-LN (fp32)
__device__ float  g_E[(long)B_ * S_ * S_];    // attention logits (fp32)

// ---------------------------------------------------------------------------
// helpers
// ---------------------------------------------------------------------------
__device__ __forceinline__ uint32_t smem_u32(const void* p) {
    uint32_t a;
    asm("{ .reg .u64 t; cvta.to.shared.u64 t, %1; cvt.u32.u64 %0, t; }"
        : "=r"(a) : "l"(p));
    return a;
}
__device__ __forceinline__ uint32_t swz(uint32_t byte) {   // SW128
    return byte ^ ((byte >> 3) & 0x70);
}
__device__ __forceinline__ void cp16(uint32_t dst, const void* src) {
    asm volatile("cp.async.cg.shared.global [%0], [%1], 16;"
                 :: "r"(dst), "l"(src) : "memory");
}
__device__ __forceinline__ void cp_commit() {
    asm volatile("cp.async.commit_group;" ::: "memory");
}
__device__ __forceinline__ void ldm4(uint32_t* r, uint32_t a) {
    asm volatile("ldmatrix.sync.aligned.m8n8.x4.shared.b16 {%0,%1,%2,%3}, [%4];"
                 : "=r"(r[0]), "=r"(r[1]), "=r"(r[2]), "=r"(r[3]) : "r"(a));
}
__device__ __forceinline__ void mma_f16(float* d, const uint32_t* a, const uint32_t* b) {
    asm volatile(
        "mma.sync.aligned.m16n8k16.row.col.f32.f16.f16.f32 "
        "{%0,%1,%2,%3}, {%4,%5,%6,%7}, {%8,%9}, {%0,%1,%2,%3};"
        : "+f"(d[0]), "+f"(d[1]), "+f"(d[2]), "+f"(d[3])
        : "r"(a[0]), "r"(a[1]), "r"(a[2]), "r"(a[3]), "r"(b[0]), "r"(b[1]));
}
__device__ __forceinline__ void st2(float* p, float a, float b) {
    *(float2*)p = make_float2(a, b);
}
__device__ __forceinline__ void st2(__half* p, float a, float b) {
    *(__half2*)p = __floats2half2_rn(a, b);
}

// ---------------------------------------------------------------------------
// Weight transpose: float in -> half out, out[c][r] = in[r][c]
// ---------------------------------------------------------------------------
__global__ void trW_k(const float* __restrict__ in, __half* __restrict__ out,
                      int rows, int cols)
{
    __shared__ float t[32][33];
    const long bs = (long)rows * cols;
    in  += blockIdx.z * bs;
    out += blockIdx.z * bs;
    const int r0 = blockIdx.y * 32, c0 = blockIdx.x * 32;
    const int tx = threadIdx.x, ty = threadIdx.y;
    #pragma unroll
    for (int i = 0; i < 32; i += 8)
        t[ty + i][tx] = in[(long)(r0 + ty + i) * cols + c0 + tx];
    __syncthreads();
    #pragma unroll
    for (int i = 0; i < 32; i += 8)
        out[(long)(c0 + ty + i) * rows + r0 + tx] = __float2half_rn(t[tx][ty + i]);
}

// ---------------------------------------------------------------------------
// V transpose (half): out[z][c][r] = in[z][r][c]
// ---------------------------------------------------------------------------
__global__ void trV_k(const __half* __restrict__ in, __half* __restrict__ out,
                      int rows, int cols)
{
    __shared__ __half t[32][33];
    const long bs = (long)rows * cols;
    in  += blockIdx.z * bs;
    out += blockIdx.z * bs;
    const int r0 = blockIdx.y * 32, c0 = blockIdx.x * 32;
    const int tx = threadIdx.x, ty = threadIdx.y;
    #pragma unroll
    for (int i = 0; i < 32; i += 8)
        t[ty + i][tx] = in[(long)(r0 + ty + i) * cols + c0 + tx];
    __syncthreads();
    #pragma unroll
    for (int i = 0; i < 32; i += 8)
        out[(long)(c0 + ty + i) * rows + r0 + tx] = t[tx][ty + i];
}

// ---------------------------------------------------------------------------
// LayerNorm: one warp per row.
// val = (res ? res : 0) + LN(in)*g + b ; writes fp16 (out16) and/or fp32 (out32)
// ---------------------------------------------------------------------------
__global__ void ln_k(const float* __restrict__ in, const float* __restrict__ res,
                     const float* __restrict__ g, const float* __restrict__ b,
                     __half* __restrict__ out16, float* __restrict__ out32, int rows)
{
    int warp = (blockIdx.x * blockDim.x + threadIdx.x) >> 5;
    int lane = threadIdx.x & 31;
    if (warp >= rows) return;

    const float4* x4 = (const float4*)(in + (long)warp * D_);
    float4 v0 = x4[lane];
    float4 v1 = x4[lane + 32];

    float s = v0.x + v0.y + v0.z + v0.w + v1.x + v1.y + v1.z + v1.w;
    #pragma unroll
    for (int o = 16; o; o >>= 1) s += __shfl_xor_sync(0xffffffffu, s, o);
    float mean = s * (1.0f / 256.0f);

    float d0x = v0.x - mean, d0y = v0.y - mean, d0z = v0.z - mean, d0w = v0.w - mean;
    float d1x = v1.x - mean, d1y = v1.y - mean, d1z = v1.z - mean, d1w = v1.w - mean;
    float q = d0x*d0x + d0y*d0y + d0z*d0z + d0w*d0w
            + d1x*d1x + d1y*d1y + d1z*d1z + d1w*d1w;
    #pragma unroll
    for (int o = 16; o; o >>= 1) q += __shfl_xor_sync(0xffffffffu, q, o);
    float inv = rsqrtf(q * (1.0f / 256.0f) + 1e-5f);

    const float4* g4 = (const float4*)g;
    const float4* b4 = (const float4*)b;
    float4 gv0 = g4[lane], gv1 = g4[lane + 32];
    float4 bv0 = b4[lane], bv1 = b4[lane + 32];

    float4 o0, o1;
    o0.x = d0x * inv * gv0.x + bv0.x;  o0.y = d0y * inv * gv0.y + bv0.y;
    o0.z = d0z * inv * gv0.z + bv0.z;  o0.w = d0w * inv * gv0.w + bv0.w;
    o1.x = d1x * inv * gv1.x + bv1.x;  o1.y = d1y * inv * gv1.y + bv1.y;
    o1.z = d1z * inv * gv1.z + bv1.z;  o1.w = d1w * inv * gv1.w + bv1.w;

    if (res) {
        const float4* r4 = (const float4*)(res + (long)warp * D_);
        float4 r0 = r4[lane], r1 = r4[lane + 32];
        o0.x += r0.x; o0.y += r0.y; o0.z += r0.z; o0.w += r0.w;
        o1.x += r1.x; o1.y += r1.y; o1.z += r1.z; o1.w += r1.w;
    }

    if (out32) {
        float4* out4 = (float4*)(out32 + (long)warp * D_);
        out4[lane]      = o0;
        out4[lane + 32] = o1;
    }
    if (out16) {
        __half2* oh = (__half2*)(out16 + (long)warp * D_);
        oh[lane * 2]            = __floats2half2_rn(o0.x, o0.y);
        oh[lane * 2 + 1]        = __floats2half2_rn(o0.z, o0.w);
        oh[(lane + 32) * 2]     = __floats2half2_rn(o1.x, o1.y);
        oh[(lane + 32) * 2 + 1] = __floats2half2_rn(o1.z, o1.w);
    }
}

// ---------------------------------------------------------------------------
// Softmax over rows of length 512 (fp32 in, fp16 out): one warp per row
// ---------------------------------------------------------------------------
__global__ void softmax_k(const float* __restrict__ E, __half* __restrict__ P, int rows)
{
    int warp = (blockIdx.x * blockDim.x + threadIdx.x) >> 5;
    int lane = threadIdx.x & 31;
    if (warp >= rows) return;

    const float4* p = (const float4*)(E + (long)warp * 512);
    float4 v[4];
    #pragma unroll
    for (int i = 0; i < 4; i++) v[i] = p[lane + 32 * i];

    float mx = -3.402823466e38f;
    #pragma unroll
    for (int i = 0; i < 4; i++)
        mx = fmaxf(mx, fmaxf(fmaxf(v[i].x, v[i].y), fmaxf(v[i].z, v[i].w)));
    #pragma unroll
    for (int o = 16; o; o >>= 1) mx = fmaxf(mx, __shfl_xor_sync(0xffffffffu, mx, o));

    float sum = 0.0f;
    #pragma unroll
    for (int i = 0; i < 4; i++) {
        v[i].x = expf(v[i].x - mx); v[i].y = expf(v[i].y - mx);
        v[i].z = expf(v[i].z - mx); v[i].w = expf(v[i].w - mx);
        sum += v[i].x + v[i].y + v[i].z + v[i].w;
    }
    #pragma unroll
    for (int o = 16; o; o >>= 1) sum += __shfl_xor_sync(0xffffffffu, sum, o);
    float r = 1.0f / sum;

    __half2* po = (__half2*)(P + (long)warp * 512);
    #pragma unroll
    for (int i = 0; i < 4; i++) {
        po[(lane + 32 * i) * 2]     = __floats2half2_rn(v[i].x * r, v[i].y * r);
        po[(lane + 32 * i) * 2 + 1] = __floats2half2_rn(v[i].z * r, v[i].w * r);
    }
}

// ---------------------------------------------------------------------------
// FP16 mma.sync GEMM 128x128x64: 128 threads (4 warps 2x2), warp tile 64x64,
// cp.async double-buffered, SW128-swizzled [128][64]-fp16 tiles (128B rows),
// ldmatrix.x4 fragments, m16n8k16 f32-accum MMA.
// Both A and B sources are fp16 [rows][K] row-major.
// EPI: 0 none | 1 +bias | 2 gelu(.+bias) | 3 res + (.+bias) | 4 attention score
// smem (dynamic 64KB): A0@0, B0@16K, A1@32K, B1@48K
// ---------------------------------------------------------------------------
template<int EPI, typename TO>
__global__ void __launch_bounds__(128, 2)
gemm_k(const __half* __restrict__ A, const __half* __restrict__ Bm,
       const float* __restrict__ bias, const float* __restrict__ res,
       TO* __restrict__ C, int M, int N, int K,
       long sA, long sB, long sC,
       const int* __restrict__ mask, const float* __restrict__ btab)
{
    extern __shared__ __half smh[];
    const uint32_t smu = smem_u32(smh);

    const int tid  = threadIdx.x;
    const int lane = tid & 31;
    const int wm   = (tid >> 5) & 1;
    const int wn   = tid >> 6;
    const int bz   = blockIdx.z;
    A  += (long)bz * sA;
    Bm += (long)bz * sB;
    C  += (long)bz * sC;
    const int bm = blockIdx.y * 128;
    const int bn = blockIdx.x * 128;

    // staging: thread t owns row t of both tiles (8 x 16B chunks each)
    const __half* Ap = A  + (long)(bm + tid) * K;
    const __half* Bp = Bm + (long)(bn + tid) * K;
    uint32_t dsw[8];
    #pragma unroll
    for (int j = 0; j < 8; j++) dsw[j] = swz(tid * 128 + j * 16);

    // fragment address bases (pre-swizzle byte offsets, add kb*32 then swz)
    uint32_t arow[4], brow[4];
    #pragma unroll
    for (int i = 0; i < 4; i++) {
        arow[i] = (wm * 64 + i * 16 + (lane & 15)) * 128 + (lane >> 4) * 16;
        brow[i] = (wn * 64 + i * 16 + (lane & 15)) * 128 + (lane >> 4) * 16;
    }
    const int g = lane >> 2;
    const int c = lane & 3;

    float acc[4][8][4];
    #pragma unroll
    for (int i = 0; i < 4; i++)
        #pragma unroll
        for (int j = 0; j < 8; j++)
            #pragma unroll
            for (int r = 0; r < 4; r++) acc[i][j][r] = 0.0f;

    const int nst = K >> 6;

    // prologue: stage tile 0 into buf 0
    #pragma unroll
    for (int j = 0; j < 8; j++) {
        cp16(smu + dsw[j],         Ap + j * 8);
        cp16(smu + 16384 + dsw[j], Bp + j * 8);
    }
    cp_commit();

    int buf = 0;
    for (int s = 0; s < nst; s++) {
        if (s + 1 < nst) {
            const int kn = (s + 1) << 6;
            const uint32_t base = smu + (buf ^ 1) * 32768;
            #pragma unroll
            for (int j = 0; j < 8; j++) {
                cp16(base + dsw[j],         Ap + kn + j * 8);
                cp16(base + 16384 + dsw[j], Bp + kn + j * 8);
            }
            cp_commit();
            asm volatile("cp.async.wait_group 1;" ::: "memory");
        } else {
            asm volatile("cp.async.wait_group 0;" ::: "memory");
        }
        __syncthreads();

        const uint32_t Au = smu + buf * 32768;
        const uint32_t Bu = Au + 16384;
        #pragma unroll
        for (int kb = 0; kb < 4; kb++) {
            uint32_t af[4][4];
            uint32_t bf[8][2];
            #pragma unroll
            for (int ma = 0; ma < 4; ma++)
                ldm4(af[ma], Au + swz(arow[ma] + kb * 32));
            #pragma unroll
            for (int np = 0; np < 4; np++) {
                uint32_t t[4];
                ldm4(t, Bu + swz(brow[np] + kb * 32));
                bf[2*np][0]   = t[0];
                bf[2*np+1][0] = t[1];
                bf[2*np][1]   = t[2];
                bf[2*np+1][1] = t[3];
            }
            #pragma unroll
            for (int ma = 0; ma < 4; ma++)
                #pragma unroll
                for (int nb = 0; nb < 8; nb++)
                    mma_f16(acc[ma][nb], af[ma], bf[nb]);
        }
        __syncthreads();
        buf ^= 1;
    }

    // ---- epilogue ----
    #pragma unroll
    for (int nb = 0; nb < 8; nb++) {
        const int col = bn + wn * 64 + nb * 8 + c * 2;

        float2 bias2 = {0.0f, 0.0f};
        if (EPI == 1 || EPI == 2 || EPI == 3)
            bias2 = *(const float2*)(bias + col);
        int mk0 = 0, mk1 = 0;
        if (EPI == 4) {
            mk0 = mask[bz * S_ + col];
            mk1 = mask[bz * S_ + col + 1];
        }

        #pragma unroll
        for (int ma = 0; ma < 4; ma++) {
            const int r0 = bm + wm * 64 + ma * 16 + g;
            const int r1 = r0 + 8;
            float d0 = acc[ma][nb][0], d1 = acc[ma][nb][1];
            float d2 = acc[ma][nb][2], d3 = acc[ma][nb][3];

            if (EPI == 1 || EPI == 2 || EPI == 3) {
                d0 += bias2.x; d1 += bias2.y;
                d2 += bias2.x; d3 += bias2.y;
            }
            if (EPI == 2) {
                d0 = 0.5f * d0 * (1.0f + erff(d0 * 0.70710678118654752f));
                d1 = 0.5f * d1 * (1.0f + erff(d1 * 0.70710678118654752f));
                d2 = 0.5f * d2 * (1.0f + erff(d2 * 0.70710678118654752f));
                d3 = 0.5f * d3 * (1.0f + erff(d3 * 0.70710678118654752f));
            }
            if (EPI == 3) {
                float2 ra = *(const float2*)(res + (long)r0 * N + col);
                float2 rb = *(const float2*)(res + (long)r1 * N + col);
                d0 += ra.x; d1 += ra.y; d2 += rb.x; d3 += rb.y;
            }
            if (EPI == 4) {
                int rel0 = col - r0;
                int rel1 = col + 1 - r0;
                int rel2 = col - r1;
                int rel3 = col + 1 - r1;
                int bk0 = (rel0 < 0) ? (511 - rel0) : rel0;
                int bk1 = (rel1 < 0) ? (511 - rel1) : rel1;
                int bk2 = (rel2 < 0) ? (511 - rel2) : rel2;
                int bk3 = (rel3 < 0) ? (511 - rel3) : rel3;
                d0 = d0 * 0.0625f + btab[bk0];
                d1 = d1 * 0.0625f + btab[bk1];
                d2 = d2 * 0.0625f + btab[bk2];
                d3 = d3 * 0.0625f + btab[bk3];
                if (mk0 == 0) { d0 = -3.402823466e38f; d2 = -3.402823466e38f; }
                if (mk1 == 0) { d1 = -3.402823466e38f; d3 = -3.402823466e38f; }
            }
            st2(C + (long)r0 * N + col, d0, d1);
            st2(C + (long)r1 * N + col, d2, d3);
        }
    }
}

#define GSMEM 65536

// ---------------------------------------------------------------------------
// Launcher
// ---------------------------------------------------------------------------
extern "C" void kernel_launch(void* const* d_in, const int* in_sizes, int n_in,
                              void* d_out, int out_size)
{
    const float* x    = (const float*)d_in[0];
    const int*   mask = (const int*)  d_in[1];
    const float* btab = (const float*)d_in[2];
    const float* ln_g = (const float*)d_in[3];
    const float* ln_b = (const float*)d_in[4];
    const float* wq   = (const float*)d_in[5];
    const float* bq   = (const float*)d_in[6];
    const float* wk   = (const float*)d_in[7];
    const float* bk   = (const float*)d_in[8];
    const float* wv   = (const float*)d_in[9];
    const float* bv   = (const float*)d_in[10];
    const float* wo   = (const float*)d_in[11];
    const float* bo   = (const float*)d_in[12];
    const float* cmg  = (const float*)d_in[13];
    const float* cmb  = (const float*)d_in[14];
    const float* w1   = (const float*)d_in[15];
    const float* b1   = (const float*)d_in[16];
    const float* w2   = (const float*)d_in[17];
    const float* b2   = (const float*)d_in[18];
    float* xo = (float*)d_out;

    __half *H16, *Q16, *K16, *V16, *VT16, *O16, *C16, *F16, *WT, *P16;
    float *H32, *T32, *E;
    cudaGetSymbolAddress((void**)&H16,  g_H16);
    cudaGetSymbolAddress((void**)&Q16,  g_Q16);
    cudaGetSymbolAddress((void**)&K16,  g_K16);
    cudaGetSymbolAddress((void**)&V16,  g_V16);
    cudaGetSymbolAddress((void**)&VT16, g_VT16);
    cudaGetSymbolAddress((void**)&O16,  g_O16);
    cudaGetSymbolAddress((void**)&C16,  g_C16);
    cudaGetSymbolAddress((void**)&F16,  g_F16);
    cudaGetSymbolAddress((void**)&WT,   g_WT16);
    cudaGetSymbolAddress((void**)&P16,  g_P16);
    cudaGetSymbolAddress((void**)&H32,  g_H32);
    cudaGetSymbolAddress((void**)&T32,  g_T32);
    cudaGetSymbolAddress((void**)&E,    g_E);

    cudaFuncSetAttribute(gemm_k<1, __half>, cudaFuncAttributeMaxDynamicSharedMemorySize, GSMEM);
    cudaFuncSetAttribute(gemm_k<4, float>,  cudaFuncAttributeMaxDynamicSharedMemorySize, GSMEM);
    cudaFuncSetAttribute(gemm_k<0, __half>, cudaFuncAttributeMaxDynamicSharedMemorySize, GSMEM);
    cudaFuncSetAttribute(gemm_k<1, float>,  cudaFuncAttributeMaxDynamicSharedMemorySize, GSMEM);
    cudaFuncSetAttribute(gemm_k<2, __half>, cudaFuncAttributeMaxDynamicSharedMemorySize, GSMEM);
    cudaFuncSetAttribute(gemm_k<3, float>,  cudaFuncAttributeMaxDynamicSharedMemorySize, GSMEM);

    // one-time weight transposes (fp32 -> fp16, transposed)
    const dim3 trWg(8, 8, 3), trB(32, 8);
    trW_k<<<trWg, trB>>>(wq, WT + 0L * 3 * WSZ, D_, D_);
    trW_k<<<trWg, trB>>>(wk, WT + 1L * 3 * WSZ, D_, D_);
    trW_k<<<trWg, trB>>>(wv, WT + 2L * 3 * WSZ, D_, D_);
    trW_k<<<trWg, trB>>>(wo, WT + 3L * 3 * WSZ, D_, D_);
    trW_k<<<trWg, trB>>>(w1, WT + 4L * 3 * WSZ, D_, D_);
    trW_k<<<trWg, trB>>>(w2, WT + 5L * 3 * WSZ, D_, D_);

    const dim3 blk(128);
    const dim3 gProj(D_ / 128, ROWS / 128, 1);   // (2, 256)
    const dim3 gScore(S_ / 128, S_ / 128, B_);   // (4, 4, 64)
    const dim3 gAV(D_ / 128, S_ / 128, B_);      // (2, 4, 64)
    const dim3 gTrV(D_ / 32, S_ / 32, B_);       // (8, 16, 64)
    const int  rowBlocks = ROWS / 8;             // 4096
    const long sQKV = (long)S_ * D_;             // 131072
    const long sE   = (long)S_ * S_;             // 262144

    for (int j = 0; j < 3; j++) {
        const float* xin = (j == 0) ? x : xo;
        const float* gj = ln_g + j * D_;
        const float* bj = ln_b + j * D_;
        const __half* wqT = WT + (0L * 3 + j) * WSZ;
        const __half* wkT = WT + (1L * 3 + j) * WSZ;
        const __half* wvT = WT + (2L * 3 + j) * WSZ;
        const __half* woT = WT + (3L * 3 + j) * WSZ;
        const __half* w1T = WT + (4L * 3 + j) * WSZ;
        const __half* w2T = WT + (5L * 3 + j) * WSZ;

        // h = LN(x) -> fp16 (GEMM input) + fp32 (residual)
        ln_k<<<rowBlocks, 256>>>(xin, nullptr, gj, bj, H16, H32, ROWS);

        // q, k, v projections -> fp16
        gemm_k<1, __half><<<gProj, blk, GSMEM>>>(H16, wqT, bq + j * D_, nullptr, Q16,
                                                 ROWS, D_, D_, 0, 0, 0, nullptr, nullptr);
        gemm_k<1, __half><<<gProj, blk, GSMEM>>>(H16, wkT, bk + j * D_, nullptr, K16,
                                                 ROWS, D_, D_, 0, 0, 0, nullptr, nullptr);
        gemm_k<1, __half><<<gProj, blk, GSMEM>>>(H16, wvT, bv + j * D_, nullptr, V16,
                                                 ROWS, D_, D_, 0, 0, 0, nullptr, nullptr);

        // V^T per batch: [b][d][s] (fp16)
        trV_k<<<gTrV, trB>>>(V16, VT16, S_, D_);

        // e = q k^T / 16 + relpos_bias, masked -> fp32 logits
        gemm_k<4, float><<<gScore, blk, GSMEM>>>(Q16, K16, nullptr, nullptr, E,
                                                 S_, S_, D_, sQKV, sQKV, sE, mask, btab);

        // p = softmax(e) -> fp16
        softmax_k<<<rowBlocks, 256>>>(E, P16, ROWS);

        // o = p @ v -> fp16
        gemm_k<0, __half><<<gAV, blk, GSMEM>>>(P16, VT16, nullptr, nullptr, O16,
                                               S_, D_, S_, sE, sQKV, sQKV, nullptr, nullptr);

        // t = o @ wo + bo -> fp32
        gemm_k<1, float><<<gProj, blk, GSMEM>>>(O16, woT, bo + j * D_, nullptr, T32,
                                                ROWS, D_, D_, 0, 0, 0, nullptr, nullptr);

        // x = h + LN(t) -> fp32
        ln_k<<<rowBlocks, 256>>>(T32, H32, gj, bj, nullptr, xo, ROWS);

        // c = LN_cm(x) -> fp16
        ln_k<<<rowBlocks, 256>>>(xo, nullptr, cmg + j * D_, cmb + j * D_, C16, nullptr, ROWS);

        // f = gelu(c @ w1 + b1) -> fp16
        gemm_k<2, __half><<<gProj, blk, GSMEM>>>(C16, w1T, b1 + j * D_, nullptr, F16,
                                                 ROWS, D_, D_, 0, 0, 0, nullptr, nullptr);

        // x = x + f @ w2 + b2 -> fp32 (in-place residual)
        gemm_k<3, float><<<gProj, blk, GSMEM>>>(F16, w2T, b2 + j * D_, xo, xo,
                                                ROWS, D_, D_, 0, 0, 0, nullptr, nullptr);
    }
}

// round 8
// speedup vs baseline: 4.0653x; 1.0758x over previous
#include <cuda_runtime.h>
#include <cuda_fp16.h>
#include <math.h>
#include <stdint.h>

// Problem dims (fixed)
#define B_   64
#define S_   512
#define D_   256
#define ROWS (B_ * S_)          // 32768
#define WSZ  (D_ * D_)          // 65536 per-layer weight size
#define L2E  1.4426950408889634f

// ---------------------------------------------------------------------------
// Scratch (device globals; no allocation allowed)
// ---------------------------------------------------------------------------
__device__ __half g_H16[ROWS * D_];
__device__ __half g_Q16[ROWS * D_];
__device__ __half g_K16[ROWS * D_];
__device__ __half g_V16[ROWS * D_];
__device__ __half g_O16[ROWS * D_];
__device__ __half g_C16[ROWS * D_];
__device__ __half g_F16[ROWS * D_];
__device__ __half g_WT16[3 * 3 * WSZ];        // wo,w1,w2 transposed fp16
__device__ __half g_WQKV[3 * 3 * WSZ];        // per-layer [768][256] fp16
__device__ float  g_H32[ROWS * D_];           // LN(x) fp32 (residual use)
__device__ float  g_T32[ROWS * D_];           // attn-out pre-LN (fp32)

// ---------------------------------------------------------------------------
// helpers
// ---------------------------------------------------------------------------
__device__ __forceinline__ uint32_t smem_u32(const void* p) {
    uint32_t a;
    asm("{ .reg .u64 t; cvta.to.shared.u64 t, %1; cvt.u32.u64 %0, t; }"
        : "=r"(a) : "l"(p));
    return a;
}
__device__ __forceinline__ uint32_t swz(uint32_t byte) {   // SW128
    return byte ^ ((byte >> 3) & 0x70);
}
__device__ __forceinline__ void cp16(uint32_t dst, const void* src) {
    asm volatile("cp.async.cg.shared.global [%0], [%1], 16;"
                 :: "r"(dst), "l"(src) : "memory");
}
__device__ __forceinline__ void cp_commit() {
    asm volatile("cp.async.commit_group;" ::: "memory");
}
__device__ __forceinline__ void ldm4(uint32_t* r, uint32_t a) {
    asm volatile("ldmatrix.sync.aligned.m8n8.x4.shared.b16 {%0,%1,%2,%3}, [%4];"
                 : "=r"(r[0]), "=r"(r[1]), "=r"(r[2]), "=r"(r[3]) : "r"(a));
}
__device__ __forceinline__ void ldm4t(uint32_t* r, uint32_t a) {
    asm volatile("ldmatrix.sync.aligned.m8n8.x4.trans.shared.b16 {%0,%1,%2,%3}, [%4];"
                 : "=r"(r[0]), "=r"(r[1]), "=r"(r[2]), "=r"(r[3]) : "r"(a));
}
__device__ __forceinline__ void mma_f16(float* d, const uint32_t* a, const uint32_t* b) {
    asm volatile(
        "mma.sync.aligned.m16n8k16.row.col.f32.f16.f16.f32 "
        "{%0,%1,%2,%3}, {%4,%5,%6,%7}, {%8,%9}, {%0,%1,%2,%3};"
        : "+f"(d[0]), "+f"(d[1]), "+f"(d[2]), "+f"(d[3])
        : "r"(a[0]), "r"(a[1]), "r"(a[2]), "r"(a[3]), "r"(b[0]), "r"(b[1]));
}
__device__ __forceinline__ uint32_t pk32(float a, float b) {
    __half2 h = __floats2half2_rn(a, b);
    return *reinterpret_cast<uint32_t*>(&h);
}
__device__ __forceinline__ void st2(float* p, float a, float b) {
    *(float2*)p = make_float2(a, b);
}
__device__ __forceinline__ void st2(__half* p, float a, float b) {
    *(__half2*)p = __floats2half2_rn(a, b);
}

// ---------------------------------------------------------------------------
// Weight transpose: float in -> half out, out[c][r] = in[r][c]; z-stride param
// ---------------------------------------------------------------------------
__global__ void trW_k(const float* __restrict__ in, __half* __restrict__ out,
                      int rows, int cols, long ostride)
{
    __shared__ float t[32][33];
    in  += blockIdx.z * (long)rows * cols;
    out += blockIdx.z * ostride;
    const int r0 = blockIdx.y * 32, c0 = blockIdx.x * 32;
    const int tx = threadIdx.x, ty = threadIdx.y;
    #pragma unroll
    for (int i = 0; i < 32; i += 8)
        t[ty + i][tx] = in[(long)(r0 + ty + i) * cols + c0 + tx];
    __syncthreads();
    #pragma unroll
    for (int i = 0; i < 32; i += 8)
        out[(long)(c0 + ty + i) * rows + r0 + tx] = __float2half_rn(t[tx][ty + i]);
}

// ---------------------------------------------------------------------------
// LayerNorm: one warp per row.
// val = (res ? res : 0) + LN(in)*g + b ; writes fp16 (out16) and/or fp32 (out32)
// ---------------------------------------------------------------------------
__global__ void ln_k(const float* __restrict__ in, const float* __restrict__ res,
                     const float* __restrict__ g, const float* __restrict__ b,
                     __half* __restrict__ out16, float* __restrict__ out32, int rows)
{
    int warp = (blockIdx.x * blockDim.x + threadIdx.x) >> 5;
    int lane = threadIdx.x & 31;
    if (warp >= rows) return;

    const float4* x4 = (const float4*)(in + (long)warp * D_);
    float4 v0 = x4[lane];
    float4 v1 = x4[lane + 32];

    float s = v0.x + v0.y + v0.z + v0.w + v1.x + v1.y + v1.z + v1.w;
    #pragma unroll
    for (int o = 16; o; o >>= 1) s += __shfl_xor_sync(0xffffffffu, s, o);
    float mean = s * (1.0f / 256.0f);

    float d0x = v0.x - mean, d0y = v0.y - mean, d0z = v0.z - mean, d0w = v0.w - mean;
    float d1x = v1.x - mean, d1y = v1.y - mean, d1z = v1.z - mean, d1w = v1.w - mean;
    float q = d0x*d0x + d0y*d0y + d0z*d0z + d0w*d0w
            + d1x*d1x + d1y*d1y + d1z*d1z + d1w*d1w;
    #pragma unroll
    for (int o = 16; o; o >>= 1) q += __shfl_xor_sync(0xffffffffu, q, o);
    float inv = rsqrtf(q * (1.0f / 256.0f) + 1e-5f);

    const float4* g4 = (const float4*)g;
    const float4* b4 = (const float4*)b;
    float4 gv0 = g4[lane], gv1 = g4[lane + 32];
    float4 bv0 = b4[lane], bv1 = b4[lane + 32];

    float4 o0, o1;
    o0.x = d0x * inv * gv0.x + bv0.x;  o0.y = d0y * inv * gv0.y + bv0.y;
    o0.z = d0z * inv * gv0.z + bv0.z;  o0.w = d0w * inv * gv0.w + bv0.w;
    o1.x = d1x * inv * gv1.x + bv1.x;  o1.y = d1y * inv * gv1.y + bv1.y;
    o1.z = d1z * inv * gv1.z + bv1.z;  o1.w = d1w * inv * gv1.w + bv1.w;

    if (res) {
        const float4* r4 = (const float4*)(res + (long)warp * D_);
        float4 r0 = r4[lane], r1 = r4[lane + 32];
        o0.x += r0.x; o0.y += r0.y; o0.z += r0.z; o0.w += r0.w;
        o1.x += r1.x; o1.y += r1.y; o1.z += r1.z; o1.w += r1.w;
    }

    if (out32) {
        float4* out4 = (float4*)(out32 + (long)warp * D_);
        out4[lane]      = o0;
        out4[lane + 32] = o1;
    }
    if (out16) {
        __half2* oh = (__half2*)(out16 + (long)warp * D_);
        oh[lane * 2]            = __floats2half2_rn(o0.x, o0.y);
        oh[lane * 2 + 1]        = __floats2half2_rn(o0.z, o0.w);
        oh[(lane + 32) * 2]     = __floats2half2_rn(o1.x, o1.y);
        oh[(lane + 32) * 2 + 1] = __floats2half2_rn(o1.z, o1.w);
    }
}

// ---------------------------------------------------------------------------
// Fused flash attention.
// Grid (2 D-halves, 4 row-blocks, 64 batches); 256 threads (8 warps x m16).
// O[b, r, dh*128 + :128] = softmax(QK^T/16 + relbias, mask) @ V[:, dh half]
// smem: btab 4KB | Q 64KB | K 2x32KB | V 2x16KB  = 164KB
// ---------------------------------------------------------------------------
__global__ void __launch_bounds__(256, 1)
flash_k(const __half* __restrict__ Qg, const __half* __restrict__ Kg,
        const __half* __restrict__ Vg, const int* __restrict__ mask,
        const float* __restrict__ btab, __half* __restrict__ Og)
{
    extern __shared__ char sm[];
    const uint32_t smu = smem_u32(sm);
    float* btab_s = (float*)sm;
    const uint32_t Qu = smu + 4096;
    const uint32_t Ku = Qu + 65536;
    const uint32_t Vu = Ku + 65536;

    const int tid = threadIdx.x, lane = tid & 31, w = tid >> 5;
    const int dh = blockIdx.x, r0 = blockIdx.y * 128, bz = blockIdx.z;

    const __half* Qp = Qg + ((long)bz * S_ + r0) * D_;
    const __half* Kp = Kg + (long)bz * S_ * D_;
    const __half* Vp = Vg + (long)bz * S_ * D_ + dh * 128;
    __half* Op = Og + ((long)bz * S_ + r0) * D_ + dh * 128;
    const int* mk = mask + bz * S_;

    // bias table -> smem (indices 0..1022 used)
    ((float4*)btab_s)[tid] = ((const float4*)btab)[tid];

    // stage Q (cp.async group 0): 128 rows x 256 halves, 4 panels [128][64]
    {
        const int qr = tid >> 1, cb = (tid & 1) * 4;
        const __half* src = Qp + (long)qr * D_;
        #pragma unroll
        for (int p = 0; p < 4; p++)
            #pragma unroll
            for (int cc = 0; cc < 4; cc++)
                cp16(Qu + p * 16384 + swz(qr * 128 + (cb + cc) * 16),
                     src + p * 64 + (cb + cc) * 8);
        cp_commit();
    }

    const int sr = tid >> 2, sch = tid & 3;
    auto stageKV = [&](int t, int bf) {
        const __half* ks = Kp + (long)(t * 64 + sr) * D_;
        const __half* vs = Vp + (long)(t * 64 + sr) * D_;
        const uint32_t kd = Ku + bf * 32768;
        const uint32_t vd = Vu + bf * 16384;
        #pragma unroll
        for (int p = 0; p < 4; p++) {
            cp16(kd + p * 8192 + swz(sr * 128 + sch * 16),       ks + p * 64 + sch * 8);
            cp16(kd + p * 8192 + swz(sr * 128 + (sch + 4) * 16), ks + p * 64 + (sch + 4) * 8);
        }
        #pragma unroll
        for (int p = 0; p < 2; p++) {
            cp16(vd + p * 8192 + swz(sr * 128 + sch * 16),       vs + p * 64 + sch * 8);
            cp16(vd + p * 8192 + swz(sr * 128 + (sch + 4) * 16), vs + p * 64 + (sch + 4) * 8);
        }
    };
    stageKV(0, 0); cp_commit();

    // wait for Q (group 0), then load Q fragments
    asm volatile("cp.async.wait_group 1;" ::: "memory");
    __syncthreads();
    uint32_t qf[16][4];
    {
        const int qrow = w * 16 + (lane & 15);
        #pragma unroll
        for (int kt = 0; kt < 16; kt++)
            ldm4(qf[kt], Qu + (kt >> 2) * 16384 +
                         swz(qrow * 128 + (kt & 3) * 32 + (lane >> 4) * 16));
    }

    const int g = lane >> 2, c = lane & 3;
    const int rowg = r0 + w * 16 + g;          // global q row (half 0); half1 = +8
    float oacc[16][4];
    #pragma unroll
    for (int i = 0; i < 16; i++)
        #pragma unroll
        for (int r = 0; r < 4; r++) oacc[i][r] = 0.0f;
    float m0 = -1e30f, m1 = -1e30f, l0 = 0.0f, l1 = 0.0f;

    for (int t = 0; t < 8; t++) {
        const int bf = t & 1;
        if (t < 7) {
            stageKV(t + 1, bf ^ 1);
            cp_commit();
            asm volatile("cp.async.wait_group 1;" ::: "memory");
        } else {
            asm volatile("cp.async.wait_group 0;" ::: "memory");
        }
        __syncthreads();

        // ---- S = Q K_tile^T (16 rows x 64 keys per warp) ----
        float sacc[8][4];
        #pragma unroll
        for (int i = 0; i < 8; i++)
            #pragma unroll
            for (int r = 0; r < 4; r++) sacc[i][r] = 0.0f;
        const uint32_t Kb = Ku + bf * 32768;
        #pragma unroll
        for (int kt = 0; kt < 16; kt++) {
            #pragma unroll
            for (int np = 0; np < 4; np++) {
                uint32_t tt[4];
                ldm4(tt, Kb + (kt >> 2) * 8192 +
                         swz((np * 16 + (lane & 15)) * 128 + (kt & 3) * 32 + (lane >> 4) * 16));
                uint32_t b0[2] = {tt[0], tt[2]}, b1[2] = {tt[1], tt[3]};
                mma_f16(sacc[2 * np],     qf[kt], b0);
                mma_f16(sacc[2 * np + 1], qf[kt], b1);
            }
        }

        // ---- online softmax ----
        float tm0 = -1e30f, tm1 = -1e30f;
        #pragma unroll
        for (int nt = 0; nt < 8; nt++) {
            const int n = t * 64 + nt * 8 + c * 2;
            const int mk0 = mk[n], mk1 = mk[n + 1];
            int rel, bk;
            rel = n - rowg;           bk = rel < 0 ? 511 - rel : rel;
            float s00 = sacc[nt][0] * 0.0625f + btab_s[bk];
            rel = n + 1 - rowg;       bk = rel < 0 ? 511 - rel : rel;
            float s01 = sacc[nt][1] * 0.0625f + btab_s[bk];
            rel = n - (rowg + 8);     bk = rel < 0 ? 511 - rel : rel;
            float s10 = sacc[nt][2] * 0.0625f + btab_s[bk];
            rel = n + 1 - (rowg + 8); bk = rel < 0 ? 511 - rel : rel;
            float s11 = sacc[nt][3] * 0.0625f + btab_s[bk];
            if (mk0 == 0) { s00 = -1e30f; s10 = -1e30f; }
            if (mk1 == 0) { s01 = -1e30f; s11 = -1e30f; }
            sacc[nt][0] = s00; sacc[nt][1] = s01; sacc[nt][2] = s10; sacc[nt][3] = s11;
            tm0 = fmaxf(tm0, fmaxf(s00, s01));
            tm1 = fmaxf(tm1, fmaxf(s10, s11));
        }
        tm0 = fmaxf(tm0, __shfl_xor_sync(0xffffffffu, tm0, 1));
        tm0 = fmaxf(tm0, __shfl_xor_sync(0xffffffffu, tm0, 2));
        tm1 = fmaxf(tm1, __shfl_xor_sync(0xffffffffu, tm1, 1));
        tm1 = fmaxf(tm1, __shfl_xor_sync(0xffffffffu, tm1, 2));
        const float mn0 = fmaxf(m0, tm0), mn1 = fmaxf(m1, tm1);
        const float cr0 = exp2f((m0 - mn0) * L2E), cr1 = exp2f((m1 - mn1) * L2E);
        m0 = mn0; m1 = mn1;
        float ps0 = 0.0f, ps1 = 0.0f;
        #pragma unroll
        for (int nt = 0; nt < 8; nt++) {
            float p00 = exp2f((sacc[nt][0] - m0) * L2E);
            float p01 = exp2f((sacc[nt][1] - m0) * L2E);
            float p10 = exp2f((sacc[nt][2] - m1) * L2E);
            float p11 = exp2f((sacc[nt][3] - m1) * L2E);
            ps0 += p00 + p01; ps1 += p10 + p11;
            sacc[nt][0] = p00; sacc[nt][1] = p01; sacc[nt][2] = p10; sacc[nt][3] = p11;
        }
        ps0 += __shfl_xor_sync(0xffffffffu, ps0, 1);
        ps0 += __shfl_xor_sync(0xffffffffu, ps0, 2);
        ps1 += __shfl_xor_sync(0xffffffffu, ps1, 1);
        ps1 += __shfl_xor_sync(0xffffffffu, ps1, 2);
        l0 = l0 * cr0 + ps0;
        l1 = l1 * cr1 + ps1;
        #pragma unroll
        for (int j = 0; j < 16; j++) {
            oacc[j][0] *= cr0; oacc[j][1] *= cr0;
            oacc[j][2] *= cr1; oacc[j][3] *= cr1;
        }

        // ---- O += P @ V_tile (P fragments straight from registers) ----
        const uint32_t Vb = Vu + bf * 16384;
        const int kb8 = (lane >> 3) & 1, nb8 = lane >> 4, li = lane & 7;
        #pragma unroll
        for (int pk = 0; pk < 4; pk++) {
            uint32_t af[4];
            af[0] = pk32(sacc[2 * pk][0],     sacc[2 * pk][1]);
            af[1] = pk32(sacc[2 * pk][2],     sacc[2 * pk][3]);
            af[2] = pk32(sacc[2 * pk + 1][0], sacc[2 * pk + 1][1]);
            af[3] = pk32(sacc[2 * pk + 1][2], sacc[2 * pk + 1][3]);
            #pragma unroll
            for (int nv = 0; nv < 8; nv++) {
                uint32_t tt[4];
                ldm4t(tt, Vb + (nv >> 2) * 8192 +
                          swz((pk * 16 + kb8 * 8 + li) * 128 + (nv & 3) * 32 + nb8 * 16));
                uint32_t b0[2] = {tt[0], tt[1]}, b1[2] = {tt[2], tt[3]};
                mma_f16(oacc[2 * nv],     af, b0);
                mma_f16(oacc[2 * nv + 1], af, b1);
            }
        }
        __syncthreads();
    }

    // ---- write O (fp16) ----
    const float rc0 = 1.0f / l0, rc1 = 1.0f / l1;
    #pragma unroll
    for (int nt = 0; nt < 16; nt++) {
        const int col = nt * 8 + c * 2;
        st2(Op + (long)(w * 16 + g) * D_ + col,     oacc[nt][0] * rc0, oacc[nt][1] * rc0);
        st2(Op + (long)(w * 16 + g + 8) * D_ + col, oacc[nt][2] * rc1, oacc[nt][3] * rc1);
    }
}
#define FSMEM (4096 + 65536 + 65536 + 32768)

// ---------------------------------------------------------------------------
// FP16 mma.sync GEMM 128x128x64 (as round 7) + EPI 5 = fused QKV routing.
// EPI: 0 none | 1 +bias | 2 gelu(.+bias) | 3 res+(.+bias) | 5 qkv (bias, route)
// ---------------------------------------------------------------------------
template<int EPI, typename TO>
__global__ void __launch_bounds__(128, 2)
gemm_k(const __half* __restrict__ A, const __half* __restrict__ Bm,
       const float* bias, const float* __restrict__ res,
       TO* C, int M, int N, int K,
       long sA, long sB, long sC,
       TO* C2, TO* C3, const float* bias2, const float* bias3)
{
    extern __shared__ __half smh[];
    const uint32_t smu = smem_u32(smh);

    const int tid  = threadIdx.x;
    const int lane = tid & 31;
    const int wm   = (tid >> 5) & 1;
    const int wn   = tid >> 6;
    const int bz   = blockIdx.z;
    A  += (long)bz * sA;
    Bm += (long)bz * sB;
    C  += (long)bz * sC;
    const int bm = blockIdx.y * 128;
    const int bn = blockIdx.x * 128;

    if (EPI == 5) {
        const int sel = bn >> 8;
        if (sel == 1) { C = C2; bias = bias2; }
        else if (sel == 2) { C = C3; bias = bias3; }
    }
    const int No = (EPI == 5) ? 256 : N;

    const __half* Ap = A  + (long)(bm + tid) * K;
    const __half* Bp = Bm + (long)(bn + tid) * K;
    uint32_t dsw[8];
    #pragma unroll
    for (int j = 0; j < 8; j++) dsw[j] = swz(tid * 128 + j * 16);

    uint32_t arow[4], brow[4];
    #pragma unroll
    for (int i = 0; i < 4; i++) {
        arow[i] = (wm * 64 + i * 16 + (lane & 15)) * 128 + (lane >> 4) * 16;
        brow[i] = (wn * 64 + i * 16 + (lane & 15)) * 128 + (lane >> 4) * 16;
    }
    const int g = lane >> 2;
    const int c = lane & 3;

    float acc[4][8][4];
    #pragma unroll
    for (int i = 0; i < 4; i++)
        #pragma unroll
        for (int j = 0; j < 8; j++)
            #pragma unroll
            for (int r = 0; r < 4; r++) acc[i][j][r] = 0.0f;

    const int nst = K >> 6;

    #pragma unroll
    for (int j = 0; j < 8; j++) {
        cp16(smu + dsw[j],         Ap + j * 8);
        cp16(smu + 16384 + dsw[j], Bp + j * 8);
    }
    cp_commit();

    int buf = 0;
    for (int s = 0; s < nst; s++) {
        if (s + 1 < nst) {
            const int kn = (s + 1) << 6;
            const uint32_t base = smu + (buf ^ 1) * 32768;
            #pragma unroll
            for (int j = 0; j < 8; j++) {
                cp16(base + dsw[j],         Ap + kn + j * 8);
                cp16(base + 16384 + dsw[j], Bp + kn + j * 8);
            }
            cp_commit();
            asm volatile("cp.async.wait_group 1;" ::: "memory");
        } else {
            asm volatile("cp.async.wait_group 0;" ::: "memory");
        }
        __syncthreads();

        const uint32_t Au = smu + buf * 32768;
        const uint32_t Bu = Au + 16384;
        #pragma unroll
        for (int kb = 0; kb < 4; kb++) {
            uint32_t af[4][4];
            uint32_t bf[8][2];
            #pragma unroll
            for (int ma = 0; ma < 4; ma++)
                ldm4(af[ma], Au + swz(arow[ma] + kb * 32));
            #pragma unroll
            for (int np = 0; np < 4; np++) {
                uint32_t t[4];
                ldm4(t, Bu + swz(brow[np] + kb * 32));
                bf[2*np][0]   = t[0];
                bf[2*np+1][0] = t[1];
                bf[2*np][1]   = t[2];
                bf[2*np+1][1] = t[3];
            }
            #pragma unroll
            for (int ma = 0; ma < 4; ma++)
                #pragma unroll
                for (int nb = 0; nb < 8; nb++)
                    mma_f16(acc[ma][nb], af[ma], bf[nb]);
        }
        __syncthreads();
        buf ^= 1;
    }

    // ---- epilogue ----
    #pragma unroll
    for (int nb = 0; nb < 8; nb++) {
        const int col  = bn + wn * 64 + nb * 8 + c * 2;
        const int colo = (EPI == 5) ? (col & 255) : col;

        float2 bias2v = {0.0f, 0.0f};
        if (EPI == 1 || EPI == 2 || EPI == 3 || EPI == 5)
            bias2v = *(const float2*)(bias + colo);

        #pragma unroll
        for (int ma = 0; ma < 4; ma++) {
            const int r0 = bm + wm * 64 + ma * 16 + g;
            const int r1 = r0 + 8;
            float d0 = acc[ma][nb][0], d1 = acc[ma][nb][1];
            float d2 = acc[ma][nb][2], d3 = acc[ma][nb][3];

            if (EPI == 1 || EPI == 2 || EPI == 3 || EPI == 5) {
                d0 += bias2v.x; d1 += bias2v.y;
                d2 += bias2v.x; d3 += bias2v.y;
            }
            if (EPI == 2) {
                d0 = 0.5f * d0 * (1.0f + erff(d0 * 0.70710678118654752f));
                d1 = 0.5f * d1 * (1.0f + erff(d1 * 0.70710678118654752f));
                d2 = 0.5f * d2 * (1.0f + erff(d2 * 0.70710678118654752f));
                d3 = 0.5f * d3 * (1.0f + erff(d3 * 0.70710678118654752f));
            }
            if (EPI == 3) {
                float2 ra = *(const float2*)(res + (long)r0 * N + col);
                float2 rb = *(const float2*)(res + (long)r1 * N + col);
                d0 += ra.x; d1 += ra.y; d2 += rb.x; d3 += rb.y;
            }
            st2(C + (long)r0 * No + colo, d0, d1);
            st2(C + (long)r1 * No + colo, d2, d3);
        }
    }
}
#define GSMEM 65536

// ---------------------------------------------------------------------------
// Launcher
// ---------------------------------------------------------------------------
extern "C" void kernel_launch(void* const* d_in, const int* in_sizes, int n_in,
                              void* d_out, int out_size)
{
    const float* x    = (const float*)d_in[0];
    const int*   mask = (const int*)  d_in[1];
    const float* btab = (const float*)d_in[2];
    const float* ln_g = (const float*)d_in[3];
    const float* ln_b = (const float*)d_in[4];
    const float* wq   = (const float*)d_in[5];
    const float* bq   = (const float*)d_in[6];
    const float* wk   = (const float*)d_in[7];
    const float* bk   = (const float*)d_in[8];
    const float* wv   = (const float*)d_in[9];
    const float* bv   = (const float*)d_in[10];
    const float* wo   = (const float*)d_in[11];
    const float* bo   = (const float*)d_in[12];
    const float* cmg  = (const float*)d_in[13];
    const float* cmb  = (const float*)d_in[14];
    const float* w1   = (const float*)d_in[15];
    const float* b1   = (const float*)d_in[16];
    const float* w2   = (const float*)d_in[17];
    const float* b2   = (const float*)d_in[18];
    float* xo = (float*)d_out;

    __half *H16, *Q16, *K16, *V16, *O16, *C16, *F16, *WT, *WQKV;
    float *H32, *T32;
    cudaGetSymbolAddress((void**)&H16,  g_H16);
    cudaGetSymbolAddress((void**)&Q16,  g_Q16);
    cudaGetSymbolAddress((void**)&K16,  g_K16);
    cudaGetSymbolAddress((void**)&V16,  g_V16);
    cudaGetSymbolAddress((void**)&O16,  g_O16);
    cudaGetSymbolAddress((void**)&C16,  g_C16);
    cudaGetSymbolAddress((void**)&F16,  g_F16);
    cudaGetSymbolAddress((void**)&WT,   g_WT16);
    cudaGetSymbolAddress((void**)&WQKV, g_WQKV);
    cudaGetSymbolAddress((void**)&H32,  g_H32);
    cudaGetSymbolAddress((void**)&T32,  g_T32);

    cudaFuncSetAttribute(gemm_k<5, __half>, cudaFuncAttributeMaxDynamicSharedMemorySize, GSMEM);
    cudaFuncSetAttribute(gemm_k<1, float>,  cudaFuncAttributeMaxDynamicSharedMemorySize, GSMEM);
    cudaFuncSetAttribute(gemm_k<2, __half>, cudaFuncAttributeMaxDynamicSharedMemorySize, GSMEM);
    cudaFuncSetAttribute(gemm_k<3, float>,  cudaFuncAttributeMaxDynamicSharedMemorySize, GSMEM);
    cudaFuncSetAttribute(flash_k, cudaFuncAttributeMaxDynamicSharedMemorySize, FSMEM);

    // one-time weight transposes (fp32 -> fp16, transposed)
    const dim3 trWg(8, 8, 3), trB(32, 8);
    trW_k<<<trWg, trB>>>(wq, WQKV + 0L * WSZ, D_, D_, 3L * WSZ);
    trW_k<<<trWg, trB>>>(wk, WQKV + 1L * WSZ, D_, D_, 3L * WSZ);
    trW_k<<<trWg, trB>>>(wv, WQKV + 2L * WSZ, D_, D_, 3L * WSZ);
    trW_k<<<trWg, trB>>>(wo, WT + 0L * 3 * WSZ, D_, D_, WSZ);
    trW_k<<<trWg, trB>>>(w1, WT + 1L * 3 * WSZ, D_, D_, WSZ);
    trW_k<<<trWg, trB>>>(w2, WT + 2L * 3 * WSZ, D_, D_, WSZ);

    const dim3 blk(128);
    const dim3 gQKV(6, ROWS / 128, 1);           // (6, 256)
    const dim3 gProj(D_ / 128, ROWS / 128, 1);   // (2, 256)
    const dim3 gFlash(2, S_ / 128, B_);          // (2, 4, 64)
    const int  rowBlocks = ROWS / 8;             // 4096

    for (int j = 0; j < 3; j++) {
        const float* xin = (j == 0) ? x : xo;
        const float* gj = ln_g + j * D_;
        const float* bj = ln_b + j * D_;
        const __half* wqkvT = WQKV + (long)j * 3 * WSZ;
        const __half* woT   = WT + (0L * 3 + j) * WSZ;
        const __half* w1T   = WT + (1L * 3 + j) * WSZ;
        const __half* w2T   = WT + (2L * 3 + j) * WSZ;

        // h = LN(x) -> fp16 + fp32
        ln_k<<<rowBlocks, 256>>>(xin, nullptr, gj, bj, H16, H32, ROWS);

        // q,k,v = h @ {wq,wk,wv} + bias   (one fused GEMM, N=768, routed)
        gemm_k<5, __half><<<gQKV, blk, GSMEM>>>(H16, wqkvT, bq + j * D_, nullptr, Q16,
                                                ROWS, 768, D_, 0, 0, 0,
                                                K16, V16, bk + j * D_, bv + j * D_);

        // o = attention(q, k, v) -> fp16  (fused flash)
        flash_k<<<gFlash, 256, FSMEM>>>(Q16, K16, V16, mask, btab, O16);

        // t = o @ wo + bo -> fp32
        gemm_k<1, float><<<gProj, blk, GSMEM>>>(O16, woT, bo + j * D_, nullptr, T32,
                                                ROWS, D_, D_, 0, 0, 0,
                                                (float*)nullptr, (float*)nullptr, nullptr, nullptr);

        // x = h + LN(t) -> fp32
        ln_k<<<rowBlocks, 256>>>(T32, H32, gj, bj, nullptr, xo, ROWS);

        // c = LN_cm(x) -> fp16
        ln_k<<<rowBlocks, 256>>>(xo, nullptr, cmg + j * D_, cmb + j * D_, C16, nullptr, ROWS);

        // f = gelu(c @ w1 + b1) -> fp16
        gemm_k<2, __half><<<gProj, blk, GSMEM>>>(C16, w1T, b1 + j * D_, nullptr, F16,
                                                 ROWS, D_, D_, 0, 0, 0,
                                                 (__half*)nullptr, (__half*)nullptr, nullptr, nullptr);

        // x = x + f @ w2 + b2 -> fp32 (in-place residual)
        gemm_k<3, float><<<gProj, blk, GSMEM>>>(F16, w2T, b2 + j * D_, xo, xo,
                                                ROWS, D_, D_, 0, 0, 0,
                                                (float*)nullptr, (float*)nullptr, nullptr, nullptr);
    }
}

// round 9
// speedup vs baseline: 4.2407x; 1.0431x over previous
#include <cuda_runtime.h>
#include <cuda_fp16.h>
#include <math.h>
#include <stdint.h>

// Problem dims (fixed)
#define B_   64
#define S_   512
#define D_   256
#define ROWS (B_ * S_)          // 32768
#define WSZ  (D_ * D_)          // 65536 per-layer weight size
#define L2E  1.4426950408889634f

// ---------------------------------------------------------------------------
// Scratch (device globals; no allocation allowed)
// ---------------------------------------------------------------------------
__device__ __half g_H16[ROWS * D_];
__device__ __half g_Q16[ROWS * D_];
__device__ __half g_K16[ROWS * D_];
__device__ __half g_V16[ROWS * D_];
__device__ __half g_O16[ROWS * D_];
__device__ __half g_C16[ROWS * D_];
__device__ __half g_F16[ROWS * D_];
__device__ __half g_WT16[3 * 3 * WSZ];        // wo,w1,w2 transposed fp16
__device__ __half g_WQKV[3 * 3 * WSZ];        // per-layer [768][256] fp16
__device__ float  g_H32[ROWS * D_];           // LN(x) fp32 (residual use)

// ---------------------------------------------------------------------------
// helpers
// ---------------------------------------------------------------------------
__device__ __forceinline__ uint32_t smem_u32(const void* p) {
    uint32_t a;
    asm("{ .reg .u64 t; cvta.to.shared.u64 t, %1; cvt.u32.u64 %0, t; }"
        : "=r"(a) : "l"(p));
    return a;
}
__device__ __forceinline__ uint32_t swz(uint32_t byte) {   // SW128
    return byte ^ ((byte >> 3) & 0x70);
}
__device__ __forceinline__ void cp16(uint32_t dst, const void* src) {
    asm volatile("cp.async.cg.shared.global [%0], [%1], 16;"
                 :: "r"(dst), "l"(src) : "memory");
}
__device__ __forceinline__ void cp_commit() {
    asm volatile("cp.async.commit_group;" ::: "memory");
}
__device__ __forceinline__ void ldm4(uint32_t* r, uint32_t a) {
    asm volatile("ldmatrix.sync.aligned.m8n8.x4.shared.b16 {%0,%1,%2,%3}, [%4];"
                 : "=r"(r[0]), "=r"(r[1]), "=r"(r[2]), "=r"(r[3]) : "r"(a));
}
__device__ __forceinline__ void ldm4t(uint32_t* r, uint32_t a) {
    asm volatile("ldmatrix.sync.aligned.m8n8.x4.trans.shared.b16 {%0,%1,%2,%3}, [%4];"
                 : "=r"(r[0]), "=r"(r[1]), "=r"(r[2]), "=r"(r[3]) : "r"(a));
}
__device__ __forceinline__ void mma_f16(float* d, const uint32_t* a, const uint32_t* b) {
    asm volatile(
        "mma.sync.aligned.m16n8k16.row.col.f32.f16.f16.f32 "
        "{%0,%1,%2,%3}, {%4,%5,%6,%7}, {%8,%9}, {%0,%1,%2,%3};"
        : "+f"(d[0]), "+f"(d[1]), "+f"(d[2]), "+f"(d[3])
        : "r"(a[0]), "r"(a[1]), "r"(a[2]), "r"(a[3]), "r"(b[0]), "r"(b[1]));
}
__device__ __forceinline__ uint32_t pk32(float a, float b) {
    __half2 h = __floats2half2_rn(a, b);
    return *reinterpret_cast<uint32_t*>(&h);
}
__device__ __forceinline__ void st2(float* p, float a, float b) {
    *(float2*)p = make_float2(a, b);
}
__device__ __forceinline__ void st2(__half* p, float a, float b) {
    *(__half2*)p = __floats2half2_rn(a, b);
}

// ---------------------------------------------------------------------------
// Weight transpose: float in -> half out, out[c][r] = in[r][c]; z-stride param
// ---------------------------------------------------------------------------
__global__ void trW_k(const float* __restrict__ in, __half* __restrict__ out,
                      int rows, int cols, long ostride)
{
    __shared__ float t[32][33];
    in  += blockIdx.z * (long)rows * cols;
    out += blockIdx.z * ostride;
    const int r0 = blockIdx.y * 32, c0 = blockIdx.x * 32;
    const int tx = threadIdx.x, ty = threadIdx.y;
    #pragma unroll
    for (int i = 0; i < 32; i += 8)
        t[ty + i][tx] = in[(long)(r0 + ty + i) * cols + c0 + tx];
    __syncthreads();
    #pragma unroll
    for (int i = 0; i < 32; i += 8)
        out[(long)(c0 + ty + i) * rows + r0 + tx] = __float2half_rn(t[tx][ty + i]);
}

// ---------------------------------------------------------------------------
// LayerNorm (used once, layer 0 input): one warp per row -> H16 + H32
// ---------------------------------------------------------------------------
__global__ void ln_k(const float* __restrict__ in,
                     const float* __restrict__ g, const float* __restrict__ b,
                     __half* __restrict__ out16, float* __restrict__ out32, int rows)
{
    int warp = (blockIdx.x * blockDim.x + threadIdx.x) >> 5;
    int lane = threadIdx.x & 31;
    if (warp >= rows) return;

    const float4* x4 = (const float4*)(in + (long)warp * D_);
    float4 v0 = x4[lane];
    float4 v1 = x4[lane + 32];

    float s = v0.x + v0.y + v0.z + v0.w + v1.x + v1.y + v1.z + v1.w;
    #pragma unroll
    for (int o = 16; o; o >>= 1) s += __shfl_xor_sync(0xffffffffu, s, o);
    float mean = s * (1.0f / 256.0f);

    float d0x = v0.x - mean, d0y = v0.y - mean, d0z = v0.z - mean, d0w = v0.w - mean;
    float d1x = v1.x - mean, d1y = v1.y - mean, d1z = v1.z - mean, d1w = v1.w - mean;
    float q = d0x*d0x + d0y*d0y + d0z*d0z + d0w*d0w
            + d1x*d1x + d1y*d1y + d1z*d1z + d1w*d1w;
    #pragma unroll
    for (int o = 16; o; o >>= 1) q += __shfl_xor_sync(0xffffffffu, q, o);
    float inv = rsqrtf(q * (1.0f / 256.0f) + 1e-5f);

    const float4* g4 = (const float4*)g;
    const float4* b4 = (const float4*)b;
    float4 gv0 = g4[lane], gv1 = g4[lane + 32];
    float4 bv0 = b4[lane], bv1 = b4[lane + 32];

    float4 o0, o1;
    o0.x = d0x * inv * gv0.x + bv0.x;  o0.y = d0y * inv * gv0.y + bv0.y;
    o0.z = d0z * inv * gv0.z + bv0.z;  o0.w = d0w * inv * gv0.w + bv0.w;
    o1.x = d1x * inv * gv1.x + bv1.x;  o1.y = d1y * inv * gv1.y + bv1.y;
    o1.z = d1z * inv * gv1.z + bv1.z;  o1.w = d1w * inv * gv1.w + bv1.w;

    float4* out4 = (float4*)(out32 + (long)warp * D_);
    out4[lane]      = o0;
    out4[lane + 32] = o1;
    __half2* oh = (__half2*)(out16 + (long)warp * D_);
    oh[lane * 2]            = __floats2half2_rn(o0.x, o0.y);
    oh[lane * 2 + 1]        = __floats2half2_rn(o0.z, o0.w);
    oh[(lane + 32) * 2]     = __floats2half2_rn(o1.x, o1.y);
    oh[(lane + 32) * 2 + 1] = __floats2half2_rn(o1.z, o1.w);
}

// ---------------------------------------------------------------------------
// Fused flash attention (same as round 8).
// ---------------------------------------------------------------------------
__global__ void __launch_bounds__(256, 1)
flash_k(const __half* __restrict__ Qg, const __half* __restrict__ Kg,
        const __half* __restrict__ Vg, const int* __restrict__ mask,
        const float* __restrict__ btab, __half* __restrict__ Og)
{
    extern __shared__ char sm[];
    const uint32_t smu = smem_u32(sm);
    float* btab_s = (float*)sm;
    const uint32_t Qu = smu + 4096;
    const uint32_t Ku = Qu + 65536;
    const uint32_t Vu = Ku + 65536;

    const int tid = threadIdx.x, lane = tid & 31, w = tid >> 5;
    const int dh = blockIdx.x, r0 = blockIdx.y * 128, bz = blockIdx.z;

    const __half* Qp = Qg + ((long)bz * S_ + r0) * D_;
    const __half* Kp = Kg + (long)bz * S_ * D_;
    const __half* Vp = Vg + (long)bz * S_ * D_ + dh * 128;
    __half* Op = Og + ((long)bz * S_ + r0) * D_ + dh * 128;
    const int* mk = mask + bz * S_;

    ((float4*)btab_s)[tid] = ((const float4*)btab)[tid];

    {
        const int qr = tid >> 1, cb = (tid & 1) * 4;
        const __half* src = Qp + (long)qr * D_;
        #pragma unroll
        for (int p = 0; p < 4; p++)
            #pragma unroll
            for (int cc = 0; cc < 4; cc++)
                cp16(Qu + p * 16384 + swz(qr * 128 + (cb + cc) * 16),
                     src + p * 64 + (cb + cc) * 8);
        cp_commit();
    }

    const int sr = tid >> 2, sch = tid & 3;
    auto stageKV = [&](int t, int bf) {
        const __half* ks = Kp + (long)(t * 64 + sr) * D_;
        const __half* vs = Vp + (long)(t * 64 + sr) * D_;
        const uint32_t kd = Ku + bf * 32768;
        const uint32_t vd = Vu + bf * 16384;
        #pragma unroll
        for (int p = 0; p < 4; p++) {
            cp16(kd + p * 8192 + swz(sr * 128 + sch * 16),       ks + p * 64 + sch * 8);
            cp16(kd + p * 8192 + swz(sr * 128 + (sch + 4) * 16), ks + p * 64 + (sch + 4) * 8);
        }
        #pragma unroll
        for (int p = 0; p < 2; p++) {
            cp16(vd + p * 8192 + swz(sr * 128 + sch * 16),       vs + p * 64 + sch * 8);
            cp16(vd + p * 8192 + swz(sr * 128 + (sch + 4) * 16), vs + p * 64 + (sch + 4) * 8);
        }
    };
    stageKV(0, 0); cp_commit();

    asm volatile("cp.async.wait_group 1;" ::: "memory");
    __syncthreads();
    uint32_t qf[16][4];
    {
        const int qrow = w * 16 + (lane & 15);
        #pragma unroll
        for (int kt = 0; kt < 16; kt++)
            ldm4(qf[kt], Qu + (kt >> 2) * 16384 +
                         swz(qrow * 128 + (kt & 3) * 32 + (lane >> 4) * 16));
    }

    const int g = lane >> 2, c = lane & 3;
    const int rowg = r0 + w * 16 + g;
    float oacc[16][4];
    #pragma unroll
    for (int i = 0; i < 16; i++)
        #pragma unroll
        for (int r = 0; r < 4; r++) oacc[i][r] = 0.0f;
    float m0 = -1e30f, m1 = -1e30f, l0 = 0.0f, l1 = 0.0f;

    for (int t = 0; t < 8; t++) {
        const int bf = t & 1;
        if (t < 7) {
            stageKV(t + 1, bf ^ 1);
            cp_commit();
            asm volatile("cp.async.wait_group 1;" ::: "memory");
        } else {
            asm volatile("cp.async.wait_group 0;" ::: "memory");
        }
        __syncthreads();

        float sacc[8][4];
        #pragma unroll
        for (int i = 0; i < 8; i++)
            #pragma unroll
            for (int r = 0; r < 4; r++) sacc[i][r] = 0.0f;
        const uint32_t Kb = Ku + bf * 32768;
        #pragma unroll
        for (int kt = 0; kt < 16; kt++) {
            #pragma unroll
            for (int np = 0; np < 4; np++) {
                uint32_t tt[4];
                ldm4(tt, Kb + (kt >> 2) * 8192 +
                         swz((np * 16 + (lane & 15)) * 128 + (kt & 3) * 32 + (lane >> 4) * 16));
                uint32_t b0[2] = {tt[0], tt[2]}, b1[2] = {tt[1], tt[3]};
                mma_f16(sacc[2 * np],     qf[kt], b0);
                mma_f16(sacc[2 * np + 1], qf[kt], b1);
            }
        }

        float tm0 = -1e30f, tm1 = -1e30f;
        #pragma unroll
        for (int nt = 0; nt < 8; nt++) {
            const int n = t * 64 + nt * 8 + c * 2;
            const int mk0 = mk[n], mk1 = mk[n + 1];
            int rel, bk;
            rel = n - rowg;           bk = rel < 0 ? 511 - rel : rel;
            float s00 = sacc[nt][0] * 0.0625f + btab_s[bk];
            rel = n + 1 - rowg;       bk = rel < 0 ? 511 - rel : rel;
            float s01 = sacc[nt][1] * 0.0625f + btab_s[bk];
            rel = n - (rowg + 8);     bk = rel < 0 ? 511 - rel : rel;
            float s10 = sacc[nt][2] * 0.0625f + btab_s[bk];
            rel = n + 1 - (rowg + 8); bk = rel < 0 ? 511 - rel : rel;
            float s11 = sacc[nt][3] * 0.0625f + btab_s[bk];
            if (mk0 == 0) { s00 = -1e30f; s10 = -1e30f; }
            if (mk1 == 0) { s01 = -1e30f; s11 = -1e30f; }
            sacc[nt][0] = s00; sacc[nt][1] = s01; sacc[nt][2] = s10; sacc[nt][3] = s11;
            tm0 = fmaxf(tm0, fmaxf(s00, s01));
            tm1 = fmaxf(tm1, fmaxf(s10, s11));
        }
        tm0 = fmaxf(tm0, __shfl_xor_sync(0xffffffffu, tm0, 1));
        tm0 = fmaxf(tm0, __shfl_xor_sync(0xffffffffu, tm0, 2));
        tm1 = fmaxf(tm1, __shfl_xor_sync(0xffffffffu, tm1, 1));
        tm1 = fmaxf(tm1, __shfl_xor_sync(0xffffffffu, tm1, 2));
        const float mn0 = fmaxf(m0, tm0), mn1 = fmaxf(m1, tm1);
        const float cr0 = exp2f((m0 - mn0) * L2E), cr1 = exp2f((m1 - mn1) * L2E);
        m0 = mn0; m1 = mn1;
        float ps0 = 0.0f, ps1 = 0.0f;
        #pragma unroll
        for (int nt = 0; nt < 8; nt++) {
            float p00 = exp2f((sacc[nt][0] - m0) * L2E);
            float p01 = exp2f((sacc[nt][1] - m0) * L2E);
            float p10 = exp2f((sacc[nt][2] - m1) * L2E);
            float p11 = exp2f((sacc[nt][3] - m1) * L2E);
            ps0 += p00 + p01; ps1 += p10 + p11;
            sacc[nt][0] = p00; sacc[nt][1] = p01; sacc[nt][2] = p10; sacc[nt][3] = p11;
        }
        ps0 += __shfl_xor_sync(0xffffffffu, ps0, 1);
        ps0 += __shfl_xor_sync(0xffffffffu, ps0, 2);
        ps1 += __shfl_xor_sync(0xffffffffu, ps1, 1);
        ps1 += __shfl_xor_sync(0xffffffffu, ps1, 2);
        l0 = l0 * cr0 + ps0;
        l1 = l1 * cr1 + ps1;
        #pragma unroll
        for (int j = 0; j < 16; j++) {
            oacc[j][0] *= cr0; oacc[j][1] *= cr0;
            oacc[j][2] *= cr1; oacc[j][3] *= cr1;
        }

        const uint32_t Vb = Vu + bf * 16384;
        const int kb8 = (lane >> 3) & 1, nb8 = lane >> 4, li = lane & 7;
        #pragma unroll
        for (int pk = 0; pk < 4; pk++) {
            uint32_t af[4];
            af[0] = pk32(sacc[2 * pk][0],     sacc[2 * pk][1]);
            af[1] = pk32(sacc[2 * pk][2],     sacc[2 * pk][3]);
            af[2] = pk32(sacc[2 * pk + 1][0], sacc[2 * pk + 1][1]);
            af[3] = pk32(sacc[2 * pk + 1][2], sacc[2 * pk + 1][3]);
            #pragma unroll
            for (int nv = 0; nv < 8; nv++) {
                uint32_t tt[4];
                ldm4t(tt, Vb + (nv >> 2) * 8192 +
                          swz((pk * 16 + kb8 * 8 + li) * 128 + (nv & 3) * 32 + nb8 * 16));
                uint32_t b0[2] = {tt[0], tt[1]}, b1[2] = {tt[2], tt[3]};
                mma_f16(oacc[2 * nv],     af, b0);
                mma_f16(oacc[2 * nv + 1], af, b1);
            }
        }
        __syncthreads();
    }

    const float rc0 = 1.0f / l0, rc1 = 1.0f / l1;
    #pragma unroll
    for (int nt = 0; nt < 16; nt++) {
        const int col = nt * 8 + c * 2;
        st2(Op + (long)(w * 16 + g) * D_ + col,     oacc[nt][0] * rc0, oacc[nt][1] * rc0);
        st2(Op + (long)(w * 16 + g + 8) * D_ + col, oacc[nt][2] * rc1, oacc[nt][3] * rc1);
    }
}
#define FSMEM (4096 + 65536 + 65536 + 32768)

// ---------------------------------------------------------------------------
// FP16 GEMM 128x128x64 (round 8) — used for QKV (EPI 5) and w1+gelu (EPI 2).
// ---------------------------------------------------------------------------
template<int EPI, typename TO>
__global__ void __launch_bounds__(128, 2)
gemm_k(const __half* __restrict__ A, const __half* __restrict__ Bm,
       const float* bias, TO* C, int M, int N, int K,
       TO* C2, TO* C3, const float* bias2, const float* bias3)
{
    extern __shared__ __half smh[];
    const uint32_t smu = smem_u32(smh);

    const int tid  = threadIdx.x;
    const int lane = tid & 31;
    const int wm   = (tid >> 5) & 1;
    const int wn   = tid >> 6;
    const int bm = blockIdx.y * 128;
    const int bn = blockIdx.x * 128;

    if (EPI == 5) {
        const int sel = bn >> 8;
        if (sel == 1) { C = C2; bias = bias2; }
        else if (sel == 2) { C = C3; bias = bias3; }
    }
    const int No = (EPI == 5) ? 256 : N;

    const __half* Ap = A  + (long)(bm + tid) * K;
    const __half* Bp = Bm + (long)(bn + tid) * K;
    uint32_t dsw[8];
    #pragma unroll
    for (int j = 0; j < 8; j++) dsw[j] = swz(tid * 128 + j * 16);

    uint32_t arow[4], brow[4];
    #pragma unroll
    for (int i = 0; i < 4; i++) {
        arow[i] = (wm * 64 + i * 16 + (lane & 15)) * 128 + (lane >> 4) * 16;
        brow[i] = (wn * 64 + i * 16 + (lane & 15)) * 128 + (lane >> 4) * 16;
    }
    const int g = lane >> 2;
    const int c = lane & 3;

    float acc[4][8][4];
    #pragma unroll
    for (int i = 0; i < 4; i++)
        #pragma unroll
        for (int j = 0; j < 8; j++)
            #pragma unroll
            for (int r = 0; r < 4; r++) acc[i][j][r] = 0.0f;

    const int nst = K >> 6;

    #pragma unroll
    for (int j = 0; j < 8; j++) {
        cp16(smu + dsw[j],         Ap + j * 8);
        cp16(smu + 16384 + dsw[j], Bp + j * 8);
    }
    cp_commit();

    int buf = 0;
    for (int s = 0; s < nst; s++) {
        if (s + 1 < nst) {
            const int kn = (s + 1) << 6;
            const uint32_t base = smu + (buf ^ 1) * 32768;
            #pragma unroll
            for (int j = 0; j < 8; j++) {
                cp16(base + dsw[j],         Ap + kn + j * 8);
                cp16(base + 16384 + dsw[j], Bp + kn + j * 8);
            }
            cp_commit();
            asm volatile("cp.async.wait_group 1;" ::: "memory");
        } else {
            asm volatile("cp.async.wait_group 0;" ::: "memory");
        }
        __syncthreads();

        const uint32_t Au = smu + buf * 32768;
        const uint32_t Bu = Au + 16384;
        #pragma unroll
        for (int kb = 0; kb < 4; kb++) {
            uint32_t af[4][4];
            uint32_t bf[8][2];
            #pragma unroll
            for (int ma = 0; ma < 4; ma++)
                ldm4(af[ma], Au + swz(arow[ma] + kb * 32));
            #pragma unroll
            for (int np = 0; np < 4; np++) {
                uint32_t t[4];
                ldm4(t, Bu + swz(brow[np] + kb * 32));
                bf[2*np][0]   = t[0];
                bf[2*np+1][0] = t[1];
                bf[2*np][1]   = t[2];
                bf[2*np+1][1] = t[3];
            }
            #pragma unroll
            for (int ma = 0; ma < 4; ma++)
                #pragma unroll
                for (int nb = 0; nb < 8; nb++)
                    mma_f16(acc[ma][nb], af[ma], bf[nb]);
        }
        __syncthreads();
        buf ^= 1;
    }

    #pragma unroll
    for (int nb = 0; nb < 8; nb++) {
        const int col  = bn + wn * 64 + nb * 8 + c * 2;
        const int colo = (EPI == 5) ? (col & 255) : col;
        float2 bv = *(const float2*)(bias + colo);

        #pragma unroll
        for (int ma = 0; ma < 4; ma++) {
            const int r0 = bm + wm * 64 + ma * 16 + g;
            const int r1 = r0 + 8;
            float d0 = acc[ma][nb][0] + bv.x, d1 = acc[ma][nb][1] + bv.y;
            float d2 = acc[ma][nb][2] + bv.x, d3 = acc[ma][nb][3] + bv.y;
            if (EPI == 2) {
                d0 = 0.5f * d0 * (1.0f + erff(d0 * 0.70710678118654752f));
                d1 = 0.5f * d1 * (1.0f + erff(d1 * 0.70710678118654752f));
                d2 = 0.5f * d2 * (1.0f + erff(d2 * 0.70710678118654752f));
                d3 = 0.5f * d3 * (1.0f + erff(d3 * 0.70710678118654752f));
            }
            st2(C + (long)r0 * No + colo, d0, d1);
            st2(C + (long)r1 * No + colo, d2, d3);
        }
    }
}
#define GSMEM 65536

// ---------------------------------------------------------------------------
// WIDE GEMM 128x256x64: 256 threads (8 warps: wm=w&1, wn=w>>1), warp 64x64.
// CTA computes full output rows -> LayerNorm fused in epilogue.
// MODE 6 (wo):  t = A@B + bias; x = h32 + LN_{g1,b1}(t); xo=x; C16=LN_{g2,b2}(x)
// MODE 7 (w2):  x = res32 + A@B + bias; xo=x; if g1: H=LN_{g1,b1}(x) -> h16,h32
// smem: 2 x (A 16KB + B 32KB) = 96KB; epilogue reduction reuses first 4KB.
// ---------------------------------------------------------------------------
template<int MODE>
__global__ void __launch_bounds__(256, 1)
gemmw_k(const __half* __restrict__ A, const __half* __restrict__ Bm,
        const float* __restrict__ bias, const float* __restrict__ res32,
        float* __restrict__ xo, __half* __restrict__ out16,
        float* __restrict__ out32,
        const float* __restrict__ g1, const float* __restrict__ b1v,
        const float* __restrict__ g2, const float* __restrict__ b2v)
{
    extern __shared__ __half smh[];
    const uint32_t smu = smem_u32(smh);
    float* red = (float*)smh;          // [128][4] sums + [128][4] sumsq = 4KB

    const int tid  = threadIdx.x;
    const int lane = tid & 31;
    const int w    = tid >> 5;
    const int wm   = w & 1;
    const int wn   = w >> 1;           // 0..3
    const int bm   = blockIdx.y * 128;

    // staging: A row = tid>>1 (4 chunks), B row = tid (8 chunks)
    const __half* Ap = A  + (long)(bm + (tid >> 1)) * D_ + (tid & 1) * 32;
    const __half* Bp = Bm + (long)tid * D_;
    uint32_t adsw[4], bdsw[8];
    #pragma unroll
    for (int j = 0; j < 4; j++)
        adsw[j] = swz((tid >> 1) * 128 + ((tid & 1) * 4 + j) * 16);
    #pragma unroll
    for (int j = 0; j < 8; j++) bdsw[j] = 16384 + swz(tid * 128 + j * 16);

    uint32_t arow[4], brow[4];
    #pragma unroll
    for (int i = 0; i < 4; i++) {
        arow[i] = (wm * 64 + i * 16 + (lane & 15)) * 128 + (lane >> 4) * 16;
        brow[i] = 16384 + swz((wn * 64 + i * 16 + (lane & 15)) * 128 + (lane >> 4) * 16);
    }
    const int g = lane >> 2;
    const int c = lane & 3;

    float acc[4][8][4];
    #pragma unroll
    for (int i = 0; i < 4; i++)
        #pragma unroll
        for (int j = 0; j < 8; j++)
            #pragma unroll
            for (int r = 0; r < 4; r++) acc[i][j][r] = 0.0f;

    // prologue
    #pragma unroll
    for (int j = 0; j < 4; j++) cp16(smu + adsw[j], Ap + j * 8);
    #pragma unroll
    for (int j = 0; j < 8; j++) cp16(smu + bdsw[j], Bp + j * 8);
    cp_commit();

    int buf = 0;
    #pragma unroll
    for (int s = 0; s < 4; s++) {
        if (s < 3) {
            const int kn = (s + 1) << 6;
            const uint32_t base = smu + (buf ^ 1) * 49152;
            #pragma unroll
            for (int j = 0; j < 4; j++) cp16(base + adsw[j], Ap + kn + j * 8);
            #pragma unroll
            for (int j = 0; j < 8; j++) cp16(base + bdsw[j], Bp + kn + j * 8);
            cp_commit();
            asm volatile("cp.async.wait_group 1;" ::: "memory");
        } else {
            asm volatile("cp.async.wait_group 0;" ::: "memory");
        }
        __syncthreads();

        const uint32_t base = smu + buf * 49152;
        #pragma unroll
        for (int kb = 0; kb < 4; kb++) {
            uint32_t af[4][4];
            uint32_t bf[8][2];
            #pragma unroll
            for (int ma = 0; ma < 4; ma++)
                ldm4(af[ma], base + swz(arow[ma] + kb * 32));
            #pragma unroll
            for (int np = 0; np < 4; np++) {
                uint32_t t[4];
                // brow already swizzled with the +16384; kb adds 32 bytes pre-swizzle:
                ldm4(t, base + 16384 + swz((brow[np] - 16384) ^ 0));
                (void)t;
                // recompute properly below
            }
            // NOTE: B fragment addresses must include kb offset pre-swizzle.
            #pragma unroll
            for (int np = 0; np < 4; np++) {
                uint32_t t[4];
                ldm4(t, base + 16384 +
                        swz((wn * 64 + np * 16 + (lane & 15)) * 128 + kb * 32 + (lane >> 4) * 16));
                bf[2*np][0]   = t[0];
                bf[2*np+1][0] = t[1];
                bf[2*np][1]   = t[2];
                bf[2*np+1][1] = t[3];
            }
            #pragma unroll
            for (int ma = 0; ma < 4; ma++)
                #pragma unroll
                for (int nb = 0; nb < 8; nb++)
                    mma_f16(acc[ma][nb], af[ma], bf[nb]);
        }
        __syncthreads();
        buf ^= 1;
    }

    // ================= epilogue with fused LayerNorm(s) =================
    const int colb = wn * 64 + c * 2;      // + nb*8
    float2 biasv[8];
    #pragma unroll
    for (int nb = 0; nb < 8; nb++) biasv[nb] = *(const float2*)(bias + colb + nb * 8);

    // t/x values into acc (+bias, + residual for MODE 7)
    #pragma unroll
    for (int ma = 0; ma < 4; ma++) {
        const long r0 = bm + wm * 64 + ma * 16 + g;
        #pragma unroll
        for (int nb = 0; nb < 8; nb++) {
            acc[ma][nb][0] += biasv[nb].x; acc[ma][nb][1] += biasv[nb].y;
            acc[ma][nb][2] += biasv[nb].x; acc[ma][nb][3] += biasv[nb].y;
            if (MODE == 7) {
                float2 ra = *(const float2*)(res32 + r0 * D_ + colb + nb * 8);
                float2 rb = *(const float2*)(res32 + (r0 + 8) * D_ + colb + nb * 8);
                acc[ma][nb][0] += ra.x; acc[ma][nb][1] += ra.y;
                acc[ma][nb][2] += rb.x; acc[ma][nb][3] += rb.y;
            }
        }
    }

    // ---- reduction helper (mean/inv over 256 cols per row) ----
    float mean0[4], inv0[4], mean1[4], inv1[4];
    auto reduce_rows = [&]() {
        #pragma unroll
        for (int ma = 0; ma < 4; ma++) {
            float s0 = 0, q0 = 0, s1 = 0, q1 = 0;
            #pragma unroll
            for (int nb = 0; nb < 8; nb++) {
                s0 += acc[ma][nb][0] + acc[ma][nb][1];
                q0 += acc[ma][nb][0] * acc[ma][nb][0] + acc[ma][nb][1] * acc[ma][nb][1];
                s1 += acc[ma][nb][2] + acc[ma][nb][3];
                q1 += acc[ma][nb][2] * acc[ma][nb][2] + acc[ma][nb][3] * acc[ma][nb][3];
            }
            s0 += __shfl_xor_sync(0xffffffffu, s0, 1); s0 += __shfl_xor_sync(0xffffffffu, s0, 2);
            q0 += __shfl_xor_sync(0xffffffffu, q0, 1); q0 += __shfl_xor_sync(0xffffffffu, q0, 2);
            s1 += __shfl_xor_sync(0xffffffffu, s1, 1); s1 += __shfl_xor_sync(0xffffffffu, s1, 2);
            q1 += __shfl_xor_sync(0xffffffffu, q1, 1); q1 += __shfl_xor_sync(0xffffffffu, q1, 2);
            if (c == 0) {
                const int r = wm * 64 + ma * 16 + g;
                red[r * 4 + wn]       = s0;  red[512 + r * 4 + wn]       = q0;
                red[(r + 8) * 4 + wn] = s1;  red[512 + (r + 8) * 4 + wn] = q1;
            }
        }
        __syncthreads();
        #pragma unroll
        for (int ma = 0; ma < 4; ma++) {
            const int r = wm * 64 + ma * 16 + g;
            float s0 = red[r*4] + red[r*4+1] + red[r*4+2] + red[r*4+3];
            float q0 = red[512+r*4] + red[512+r*4+1] + red[512+r*4+2] + red[512+r*4+3];
            float s1 = red[(r+8)*4] + red[(r+8)*4+1] + red[(r+8)*4+2] + red[(r+8)*4+3];
            float q1 = red[512+(r+8)*4] + red[512+(r+8)*4+1] + red[512+(r+8)*4+2] + red[512+(r+8)*4+3];
            mean0[ma] = s0 * (1.0f / 256.0f);
            inv0[ma]  = rsqrtf(q0 * (1.0f / 256.0f) - mean0[ma] * mean0[ma] + 1e-5f);
            mean1[ma] = s1 * (1.0f / 256.0f);
            inv1[ma]  = rsqrtf(q1 * (1.0f / 256.0f) - mean1[ma] * mean1[ma] + 1e-5f);
        }
        __syncthreads();   // red reusable afterwards
    };

    __syncthreads();       // smem staging -> reduction buffer reuse
    if (MODE == 7 && g1 == nullptr) {
        // plain residual output (last layer)
        #pragma unroll
        for (int ma = 0; ma < 4; ma++) {
            const long r0 = bm + wm * 64 + ma * 16 + g;
            #pragma unroll
            for (int nb = 0; nb < 8; nb++) {
                st2(xo + r0 * D_ + colb + nb * 8,       acc[ma][nb][0], acc[ma][nb][1]);
                st2(xo + (r0 + 8) * D_ + colb + nb * 8, acc[ma][nb][2], acc[ma][nb][3]);
            }
        }
        return;
    }

    reduce_rows();   // stats of t (MODE 6) or x (MODE 7)

    float2 g1v[8], b1vv[8];
    #pragma unroll
    for (int nb = 0; nb < 8; nb++) {
        g1v[nb]  = *(const float2*)(g1 + colb + nb * 8);
        b1vv[nb] = *(const float2*)(b1v + colb + nb * 8);
    }

    if (MODE == 7) {
        // write xo = x ; out = LN(x)
        #pragma unroll
        for (int ma = 0; ma < 4; ma++) {
            const long r0 = bm + wm * 64 + ma * 16 + g;
            #pragma unroll
            for (int nb = 0; nb < 8; nb++) {
                const int cc = colb + nb * 8;
                float x0 = acc[ma][nb][0], x1 = acc[ma][nb][1];
                float x2 = acc[ma][nb][2], x3 = acc[ma][nb][3];
                st2(xo + r0 * D_ + cc, x0, x1);
                st2(xo + (r0 + 8) * D_ + cc, x2, x3);
                float h0 = (x0 - mean0[ma]) * inv0[ma] * g1v[nb].x + b1vv[nb].x;
                float h1 = (x1 - mean0[ma]) * inv0[ma] * g1v[nb].y + b1vv[nb].y;
                float h2 = (x2 - mean1[ma]) * inv1[ma] * g1v[nb].x + b1vv[nb].x;
                float h3 = (x3 - mean1[ma]) * inv1[ma] * g1v[nb].y + b1vv[nb].y;
                st2(out32 + r0 * D_ + cc, h0, h1);
                st2(out32 + (r0 + 8) * D_ + cc, h2, h3);
                st2(out16 + r0 * D_ + cc, h0, h1);
                st2(out16 + (r0 + 8) * D_ + cc, h2, h3);
            }
        }
        return;
    }

    // MODE 6: x = h32 + LN(t); second LN for C16
    #pragma unroll
    for (int ma = 0; ma < 4; ma++) {
        const long r0 = bm + wm * 64 + ma * 16 + g;
        #pragma unroll
        for (int nb = 0; nb < 8; nb++) {
            const int cc = colb + nb * 8;
            float2 ha = *(const float2*)(res32 + r0 * D_ + cc);
            float2 hb = *(const float2*)(res32 + (r0 + 8) * D_ + cc);
            acc[ma][nb][0] = ha.x + (acc[ma][nb][0] - mean0[ma]) * inv0[ma] * g1v[nb].x + b1vv[nb].x;
            acc[ma][nb][1] = ha.y + (acc[ma][nb][1] - mean0[ma]) * inv0[ma] * g1v[nb].y + b1vv[nb].y;
            acc[ma][nb][2] = hb.x + (acc[ma][nb][2] - mean1[ma]) * inv1[ma] * g1v[nb].x + b1vv[nb].x;
            acc[ma][nb][3] = hb.y + (acc[ma][nb][3] - mean1[ma]) * inv1[ma] * g1v[nb].y + b1vv[nb].y;
        }
    }
    reduce_rows();   // stats of x

    #pragma unroll
    for (int nb = 0; nb < 8; nb++) {
        g1v[nb]  = *(const float2*)(g2 + colb + nb * 8);
        b1vv[nb] = *(const float2*)(b2v + colb + nb * 8);
    }
    #pragma unroll
    for (int ma = 0; ma < 4; ma++) {
        const long r0 = bm + wm * 64 + ma * 16 + g;
        #pragma unroll
        for (int nb = 0; nb < 8; nb++) {
            const int cc = colb + nb * 8;
            float x0 = acc[ma][nb][0], x1 = acc[ma][nb][1];
            float x2 = acc[ma][nb][2], x3 = acc[ma][nb][3];
            st2(xo + r0 * D_ + cc, x0, x1);
            st2(xo + (r0 + 8) * D_ + cc, x2, x3);
            float c0 = (x0 - mean0[ma]) * inv0[ma] * g1v[nb].x + b1vv[nb].x;
            float c1 = (x1 - mean0[ma]) * inv0[ma] * g1v[nb].y + b1vv[nb].y;
            float c2 = (x2 - mean1[ma]) * inv1[ma] * g1v[nb].x + b1vv[nb].x;
            float c3 = (x3 - mean1[ma]) * inv1[ma] * g1v[nb].y + b1vv[nb].y;
            st2(out16 + r0 * D_ + cc, c0, c1);
            st2(out16 + (r0 + 8) * D_ + cc, c2, c3);
        }
    }
}
#define WSMEM 98304

// ---------------------------------------------------------------------------
// Launcher
// ---------------------------------------------------------------------------
extern "C" void kernel_launch(void* const* d_in, const int* in_sizes, int n_in,
                              void* d_out, int out_size)
{
    const float* x    = (const float*)d_in[0];
    const int*   mask = (const int*)  d_in[1];
    const float* btab = (const float*)d_in[2];
    const float* ln_g = (const float*)d_in[3];
    const float* ln_b = (const float*)d_in[4];
    const float* wq   = (const float*)d_in[5];
    const float* bq   = (const float*)d_in[6];
    const float* wk   = (const float*)d_in[7];
    const float* bk   = (const float*)d_in[8];
    const float* wv   = (const float*)d_in[9];
    const float* bv   = (const float*)d_in[10];
    const float* wo   = (const float*)d_in[11];
    const float* bo   = (const float*)d_in[12];
    const float* cmg  = (const float*)d_in[13];
    const float* cmb  = (const float*)d_in[14];
    const float* w1   = (const float*)d_in[15];
    const float* b1   = (const float*)d_in[16];
    const float* w2   = (const float*)d_in[17];
    const float* b2   = (const float*)d_in[18];
    float* xo = (float*)d_out;

    __half *H16, *Q16, *K16, *V16, *O16, *C16, *F16, *WT, *WQKV;
    float *H32;
    cudaGetSymbolAddress((void**)&H16,  g_H16);
    cudaGetSymbolAddress((void**)&Q16,  g_Q16);
    cudaGetSymbolAddress((void**)&K16,  g_K16);
    cudaGetSymbolAddress((void**)&V16,  g_V16);
    cudaGetSymbolAddress((void**)&O16,  g_O16);
    cudaGetSymbolAddress((void**)&C16,  g_C16);
    cudaGetSymbolAddress((void**)&F16,  g_F16);
    cudaGetSymbolAddress((void**)&WT,   g_WT16);
    cudaGetSymbolAddress((void**)&WQKV, g_WQKV);
    cudaGetSymbolAddress((void**)&H32,  g_H32);

    cudaFuncSetAttribute(gemm_k<5, __half>, cudaFuncAttributeMaxDynamicSharedMemorySize, GSMEM);
    cudaFuncSetAttribute(gemm_k<2, __half>, cudaFuncAttributeMaxDynamicSharedMemorySize, GSMEM);
    cudaFuncSetAttribute(gemmw_k<6>, cudaFuncAttributeMaxDynamicSharedMemorySize, WSMEM);
    cudaFuncSetAttribute(gemmw_k<7>, cudaFuncAttributeMaxDynamicSharedMemorySize, WSMEM);
    cudaFuncSetAttribute(flash_k, cudaFuncAttributeMaxDynamicSharedMemorySize, FSMEM);

    // one-time weight transposes (fp32 -> fp16, transposed)
    const dim3 trWg(8, 8, 3), trB(32, 8);
    trW_k<<<trWg, trB>>>(wq, WQKV + 0L * WSZ, D_, D_, 3L * WSZ);
    trW_k<<<trWg, trB>>>(wk, WQKV + 1L * WSZ, D_, D_, 3L * WSZ);
    trW_k<<<trWg, trB>>>(wv, WQKV + 2L * WSZ, D_, D_, 3L * WSZ);
    trW_k<<<trWg, trB>>>(wo, WT + 0L * 3 * WSZ, D_, D_, WSZ);
    trW_k<<<trWg, trB>>>(w1, WT + 1L * 3 * WSZ, D_, D_, WSZ);
    trW_k<<<trWg, trB>>>(w2, WT + 2L * 3 * WSZ, D_, D_, WSZ);

    const dim3 gQKV(6, ROWS / 128, 1);
    const dim3 gProj(D_ / 128, ROWS / 128, 1);
    const dim3 gWide(1, ROWS / 128, 1);
    const dim3 gFlash(2, S_ / 128, B_);
    const int  rowBlocks = ROWS / 8;

    // layer-0 input LN
    ln_k<<<rowBlocks, 256>>>(x, ln_g, ln_b, H16, H32, ROWS);

    for (int j = 0; j < 3; j++) {
        const float* gj = ln_g + j * D_;
        const float* bj = ln_b + j * D_;
        const __half* wqkvT = WQKV + (long)j * 3 * WSZ;
        const __half* woT   = WT + (0L * 3 + j) * WSZ;
        const __half* w1T   = WT + (1L * 3 + j) * WSZ;
        const __half* w2T   = WT + (2L * 3 + j) * WSZ;

        // q,k,v = h @ {wq,wk,wv} + bias (fused, routed)
        gemm_k<5, __half><<<gQKV, 128, GSMEM>>>(H16, wqkvT, bq + j * D_, Q16,
                                                ROWS, 768, D_,
                                                K16, V16, bk + j * D_, bv + j * D_);

        // o = attention(q, k, v)
        flash_k<<<gFlash, 256, FSMEM>>>(Q16, K16, V16, mask, btab, O16);

        // x = h + LN(o@wo+bo); c = LN_cm(x)   (fused wide GEMM)
        gemmw_k<6><<<gWide, 256, WSMEM>>>(O16, woT, bo + j * D_, H32,
                                          xo, C16, nullptr,
                                          gj, bj, cmg + j * D_, cmb + j * D_);

        // f = gelu(c @ w1 + b1)
        gemm_k<2, __half><<<gProj, 128, GSMEM>>>(C16, w1T, b1 + j * D_, F16,
                                                 ROWS, D_, D_,
                                                 (__half*)nullptr, (__half*)nullptr, nullptr, nullptr);

        // x = x + f@w2 + b2 ; h_next = LN(x) (layers 0,1)
        const bool last = (j == 2);
        gemmw_k<7><<<gWide, 256, WSMEM>>>(F16, w2T, b2 + j * D_, xo,
                                          xo, last ? nullptr : H16,
                                          last ? nullptr : H32,
                                          last ? nullptr : ln_g + (j + 1) * D_,
                                          last ? nullptr : ln_b + (j + 1) * D_,
                                          nullptr, nullptr);
    }
}